// round 1
// baseline (speedup 1.0000x reference)
#include <cuda_runtime.h>
#include <math.h>

// Problem constants
// B=2, T=1024, D=1024, NH=16, HD=64, H=64, M=16, N_a = H*M*(M+1) = 17408
#define BT 2048
#define DD 1024
#define NA 17408

// ---------------- scratch buffers (static device globals; no allocation) ----
__device__ float g_h   [BT * DD];
__device__ float g_qkv [BT * 3 * DD];
__device__ float g_qr  [2 * 16 * 1024 * 64];
__device__ float g_kr  [2 * 16 * 1024 * 64];
__device__ float g_vb  [2 * 16 * 1024 * 64];
__device__ float g_o   [BT * DD];
__device__ float g_x2  [BT * DD];
__device__ float g_h2  [BT * DD];
__device__ float g_vv  [BT * DD];
__device__ float g_gates[(size_t)BT * NA];           // raw gate logits
__device__ float g_Apack[(size_t)2 * 64 * 1024 * 256]; // [b][h][t][i][j] softmaxed A
__device__ float g_bv  [2 * 64 * 1024 * 16];          // [b][h][t][m] = a0 * v
__device__ float g_hout[BT * DD];

// ---------------- RMSNorm: one block per row of 1024 -----------------------
__global__ __launch_bounds__(256) void rmsnorm_kernel(
    const float* __restrict__ x, const float* __restrict__ w, float* __restrict__ out)
{
    int row = blockIdx.x;
    const float4* xr = (const float4*)(x + (size_t)row * DD);
    float4 xv = xr[threadIdx.x];                       // 256 threads * 4 = 1024
    float ss = xv.x*xv.x + xv.y*xv.y + xv.z*xv.z + xv.w*xv.w;
    #pragma unroll
    for (int o = 16; o > 0; o >>= 1) ss += __shfl_xor_sync(0xFFFFFFFFu, ss, o);
    __shared__ float red[8];
    if ((threadIdx.x & 31) == 0) red[threadIdx.x >> 5] = ss;
    __syncthreads();
    float tot = red[0]+red[1]+red[2]+red[3]+red[4]+red[5]+red[6]+red[7];
    float r = rsqrtf(tot * (1.0f/1024.0f) + 1e-5f);
    const float4* w4 = (const float4*)w;
    float4 wv = w4[threadIdx.x];
    float4 ov = make_float4(xv.x*r*wv.x, xv.y*r*wv.y, xv.z*r*wv.z, xv.w*r*wv.w);
    ((float4*)(out + (size_t)row * DD))[threadIdx.x] = ov;
}

// ---------------- SGEMM: C[M,N] = A[M,K] @ B[K,N] (+ Cin), row-major -------
// Requires M%128==0, N%128==0, K%8==0 (true for all calls here).
#define GBM 128
#define GBN 128
#define GBK 8
__global__ __launch_bounds__(256) void sgemm(
    const float* __restrict__ A, const float* __restrict__ B,
    const float* __restrict__ Cin, float* __restrict__ C,
    int Mm, int Nn, int Kk)
{
    __shared__ float As[GBK][GBM];
    __shared__ float Bs[GBK][GBN];
    int tid = threadIdx.x;
    const int brow = blockIdx.y * GBM;
    const int bcol = blockIdx.x * GBN;

    int arow  = tid >> 1;            // 0..127
    int acol4 = (tid & 1) * 4;       // 0 or 4
    int brl   = tid >> 5;            // 0..7
    int bcl   = (tid & 31) * 4;      // 0..124

    int tr = (tid >> 4) * 8;         // 0..120
    int tc = (tid & 15) * 8;

    float acc[8][8];
    #pragma unroll
    for (int i = 0; i < 8; i++)
        #pragma unroll
        for (int j = 0; j < 8; j++) acc[i][j] = 0.f;

    for (int k0 = 0; k0 < Kk; k0 += GBK) {
        float4 av = *(const float4*)(A + (size_t)(brow + arow) * Kk + k0 + acol4);
        As[acol4+0][arow] = av.x;
        As[acol4+1][arow] = av.y;
        As[acol4+2][arow] = av.z;
        As[acol4+3][arow] = av.w;
        float4 bv = *(const float4*)(B + (size_t)(k0 + brl) * Nn + bcol + bcl);
        *(float4*)&Bs[brl][bcl] = bv;
        __syncthreads();
        #pragma unroll
        for (int k = 0; k < GBK; k++) {
            float ar[8], br[8];
            #pragma unroll
            for (int i = 0; i < 8; i++) ar[i] = As[k][tr + i];
            #pragma unroll
            for (int j = 0; j < 8; j++) br[j] = Bs[k][tc + j];
            #pragma unroll
            for (int i = 0; i < 8; i++)
                #pragma unroll
                for (int j = 0; j < 8; j++)
                    acc[i][j] = fmaf(ar[i], br[j], acc[i][j]);
        }
        __syncthreads();
    }

    #pragma unroll
    for (int i = 0; i < 8; i++) {
        size_t row = brow + tr + i;
        #pragma unroll
        for (int j = 0; j < 8; j += 4) {
            size_t col = bcol + tc + j;
            float4 ov = make_float4(acc[i][j], acc[i][j+1], acc[i][j+2], acc[i][j+3]);
            if (Cin) {
                float4 rv = *(const float4*)(Cin + row * Nn + col);
                ov.x += rv.x; ov.y += rv.y; ov.z += rv.z; ov.w += rv.w;
            }
            *(float4*)(C + row * Nn + col) = ov;
        }
    }
}

// ---------------- RoPE + repack to [b][h][t][hd] ---------------------------
__global__ __launch_bounds__(256) void rope_kernel()
{
    int idx = blockIdx.x * 256 + threadIdx.x;       // 2^21 total
    int d  = idx & 63;
    int hh = (idx >> 6) & 15;
    int t  = (idx >> 10) & 1023;
    int b  = idx >> 20;
    const float* base = g_qkv + (size_t)(b * 1024 + t) * 3072;
    float qv = base[hh * 64 + d];
    float kv = base[1024 + hh * 64 + d];
    float vv = base[2048 + hh * 64 + d];
    int i = d & 31;
    float inv = powf(10000.0f, -(float)i * (1.0f / 32.0f));
    float f = (float)t * inv;
    float sn, cs;
    sincosf(f, &sn, &cs);
    float q2 = (d < 32) ? -base[hh*64 + d + 32] : base[hh*64 + d - 32];
    float k2 = (d < 32) ? -base[1024 + hh*64 + d + 32] : base[1024 + hh*64 + d - 32];
    size_t oi = ((size_t)(b * 16 + hh) * 1024 + t) * 64 + d;
    g_qr[oi] = qv * cs + q2 * sn;
    g_kr[oi] = kv * cs + k2 * sn;
    g_vb[oi] = vv;
}

// ---------------- Flash attention (fp32), causal ---------------------------
// grid (16 qtiles, 16 heads, 2 batch), 64 threads (1 q row / thread)
__global__ __launch_bounds__(64) void attn_kernel()
{
    int bh = blockIdx.z * 16 + blockIdx.y;
    int q0 = blockIdx.x * 64;
    int t  = q0 + threadIdx.x;

    const float* qrow = g_qr + ((size_t)bh * 1024 + t) * 64;
    float q[64];
    #pragma unroll
    for (int d = 0; d < 64; d++) q[d] = qrow[d];

    float m = -1e30f, l = 0.f;
    float oa[64];
    #pragma unroll
    for (int d = 0; d < 64; d++) oa[d] = 0.f;

    __shared__ float Ks[32][64];
    __shared__ float Vs[32][64];

    for (int s0 = 0; s0 < q0 + 64; s0 += 32) {
        for (int i = threadIdx.x; i < 512; i += 64) {
            int r = i >> 4, c4 = (i & 15) * 4;
            *(float4*)&Ks[r][c4] = *(const float4*)(g_kr + ((size_t)bh*1024 + s0 + r)*64 + c4);
            *(float4*)&Vs[r][c4] = *(const float4*)(g_vb + ((size_t)bh*1024 + s0 + r)*64 + c4);
        }
        __syncthreads();
        float sc[32];
        float mt = m;
        #pragma unroll
        for (int j = 0; j < 32; j++) {
            float dot = 0.f;
            #pragma unroll
            for (int d = 0; d < 64; d++) dot = fmaf(q[d], Ks[j][d], dot);
            sc[j] = (s0 + j <= t) ? dot * 0.125f : -1e30f;
            mt = fmaxf(mt, sc[j]);
        }
        float corr = __expf(m - mt);
        l *= corr;
        #pragma unroll
        for (int d = 0; d < 64; d++) oa[d] *= corr;
        #pragma unroll
        for (int j = 0; j < 32; j++) {
            float p = __expf(sc[j] - mt);
            l += p;
            #pragma unroll
            for (int d = 0; d < 64; d++) oa[d] = fmaf(p, Vs[j][d], oa[d]);
        }
        m = mt;
        __syncthreads();
    }
    float inv = 1.0f / l;
    int b = bh >> 4, hh = bh & 15;
    float* orow = g_o + ((size_t)(b * 1024) + t) * 1024 + hh * 64;
    #pragma unroll
    for (int d = 0; d < 64; d++) orow[d] = oa[d] * inv;
}

// ---------------- gate softmax + pack A / (a0*v) ---------------------------
__global__ __launch_bounds__(256) void gate_pack_kernel()
{
    int idx = blockIdx.x * 256 + threadIdx.x;       // B*T*H*M = 2^21
    int mm = idx & 15;
    int hh = (idx >> 4) & 63;
    int t  = (idx >> 10) & 1023;
    int b  = idx >> 20;
    const float* g = g_gates + (size_t)idx * 17;
    float e[17];
    float mx = -1e30f;
    #pragma unroll
    for (int k = 0; k < 17; k++) { e[k] = g[k]; mx = fmaxf(mx, e[k]); }
    float sum = 0.f;
    #pragma unroll
    for (int k = 0; k < 17; k++) { e[k] = __expf(e[k] - mx); sum += e[k]; }
    float inv = 1.0f / sum;
    int bh = b * 64 + hh;
    float* Ad = g_Apack + (((size_t)bh * 1024 + t) * 16 + mm) * 16;
    #pragma unroll
    for (int k = 0; k < 16; k++) Ad[k] = e[k + 1] * inv;
    float v = g_vv[((size_t)(b * 1024 + t)) * 1024 + hh * 16 + mm];
    g_bv[((size_t)bh * 1024 + t) * 16 + mm] = e[0] * inv * v;
}

// ---------------- sequential gated scan over T -----------------------------
// grid = B*H = 128 blocks, 128 threads. Lanes 0..15 of warp 0 compute the
// 16x16 matvec chain; all 128 threads double-buffer A chunks (16 steps) so
// DRAM latency is hidden behind the serial compute.
__global__ __launch_bounds__(128) void scan_kernel()
{
    int bh = blockIdx.x;               // b*64 + h
    int b = bh >> 6, hh = bh & 63;
    __shared__ float Abuf[2][16 * 256];
    __shared__ float bvbuf[2][16 * 16];
    __shared__ float st[16];
    const float4* Ap = (const float4*)(g_Apack + (size_t)bh * 1024 * 256);
    const float4* Bp = (const float4*)(g_bv + (size_t)bh * 1024 * 16);
    int tid = threadIdx.x;
    if (tid < 16) st[tid] = 0.f;

    #pragma unroll
    for (int k = 0; k < 8; k++)
        ((float4*)Abuf[0])[tid + k * 128] = Ap[tid + k * 128];
    if (tid < 64) ((float4*)bvbuf[0])[tid] = Bp[tid];
    __syncthreads();

    int cur = 0;
    for (int c = 0; c < 64; c++) {
        float4 pf[8];
        float4 pb;
        if (c < 63) {
            #pragma unroll
            for (int k = 0; k < 8; k++)
                pf[k] = Ap[(size_t)(c + 1) * 1024 + tid + k * 128];
            if (tid < 64) pb = Bp[(size_t)(c + 1) * 64 + tid];
        }
        if (tid < 16) {
            const float4* Ab = (const float4*)Abuf[cur];
            const float* bvv = bvbuf[cur];
            float* hrow = g_hout + ((size_t)(b * 1024 + c * 16)) * 1024 + hh * 16 + tid;
            #pragma unroll 4
            for (int s = 0; s < 16; s++) {
                float4 s0 = *(const float4*)&st[0];
                float4 s1 = *(const float4*)&st[4];
                float4 s2 = *(const float4*)&st[8];
                float4 s3 = *(const float4*)&st[12];
                float4 a0 = Ab[s * 64 + tid * 4 + 0];
                float4 a1 = Ab[s * 64 + tid * 4 + 1];
                float4 a2 = Ab[s * 64 + tid * 4 + 2];
                float4 a3 = Ab[s * 64 + tid * 4 + 3];
                float p0 = fmaf(a0.x, s0.x, fmaf(a0.y, s0.y, fmaf(a0.z, s0.z, a0.w * s0.w)));
                float p1 = fmaf(a1.x, s1.x, fmaf(a1.y, s1.y, fmaf(a1.z, s1.z, a1.w * s1.w)));
                float p2 = fmaf(a2.x, s2.x, fmaf(a2.y, s2.y, fmaf(a2.z, s2.z, a2.w * s2.w)));
                float p3 = fmaf(a3.x, s3.x, fmaf(a3.y, s3.y, fmaf(a3.z, s3.z, a3.w * s3.w)));
                float acc = bvv[s * 16 + tid] + ((p0 + p1) + (p2 + p3));
                __syncwarp(0xFFFF);
                st[tid] = acc;
                __syncwarp(0xFFFF);
                hrow[(size_t)s * 1024] = acc;
            }
        }
        if (c < 63) {
            #pragma unroll
            for (int k = 0; k < 8; k++)
                ((float4*)Abuf[cur ^ 1])[tid + k * 128] = pf[k];
            if (tid < 64) ((float4*)bvbuf[cur ^ 1])[tid] = pb;
        }
        __syncthreads();
        cur ^= 1;
    }
}

// ---------------- launch ----------------------------------------------------
extern "C" void kernel_launch(void* const* d_in, const int* in_sizes, int n_in,
                              void* d_out, int out_size)
{
    const float* x    = (const float*)d_in[0];
    const float* anw  = (const float*)d_in[1];
    const float* wqkv = (const float*)d_in[2];
    const float* wao  = (const float*)d_in[3];
    const float* lnw  = (const float*)d_in[4];
    const float* wv   = (const float*)d_in[5];
    const float* wa   = (const float*)d_in[6];
    const float* wop  = (const float*)d_in[7];
    float* out = (float*)d_out;

    float *ph, *pqkv, *po, *px2, *ph2, *pvv, *pg, *phout;
    cudaGetSymbolAddress((void**)&ph,    g_h);
    cudaGetSymbolAddress((void**)&pqkv,  g_qkv);
    cudaGetSymbolAddress((void**)&po,    g_o);
    cudaGetSymbolAddress((void**)&px2,   g_x2);
    cudaGetSymbolAddress((void**)&ph2,   g_h2);
    cudaGetSymbolAddress((void**)&pvv,   g_vv);
    cudaGetSymbolAddress((void**)&pg,    g_gates);
    cudaGetSymbolAddress((void**)&phout, g_hout);

    // 1. h = rmsnorm(x)
    rmsnorm_kernel<<<BT, 256>>>(x, anw, ph);
    // 2. qkv = h @ w_qkv
    sgemm<<<dim3(3072 / GBN, BT / GBM), 256>>>(ph, wqkv, nullptr, pqkv, BT, 3072, DD);
    // 3. rope + repack
    rope_kernel<<<(2 * 1024 * 16 * 64) / 256, 256>>>();
    // 4. causal attention
    attn_kernel<<<dim3(16, 16, 2), 64>>>();
    // 5. x2 = x + o @ w_attn_out
    sgemm<<<dim3(DD / GBN, BT / GBM), 256>>>(po, wao, x, px2, BT, DD, DD);
    // 6. h2 = rmsnorm(x2)
    rmsnorm_kernel<<<BT, 256>>>(px2, lnw, ph2);
    // 7. vv = h2 @ w_v
    sgemm<<<dim3(DD / GBN, BT / GBM), 256>>>(ph2, wv, nullptr, pvv, BT, DD, DD);
    // 8. gates = h2 @ w_a   (the big one: N=17408)
    sgemm<<<dim3(NA / GBN, BT / GBM), 256>>>(ph2, wa, nullptr, pg, BT, NA, DD);
    // 9. softmax gates -> A pack + a0*v
    gate_pack_kernel<<<(2 * 1024 * 64 * 16) / 256, 256>>>();
    // 10. sequential scan
    scan_kernel<<<128, 128>>>();
    // 11. out = x2 + h_out @ w_out_proj
    sgemm<<<dim3(DD / GBN, BT / GBM), 256>>>(phout, wop, px2, out, BT, DD, DD);
}

// round 2
// speedup vs baseline: 1.5826x; 1.5826x over previous
#include <cuda_runtime.h>
#include <math.h>

// B=2, T=1024, D=1024, NH=16, HD=64, H=64, M=16, N_a = H*M*(M+1) = 17408
#define BT 2048
#define DD 1024
#define NA 17408

// ---------------- scratch buffers -------------------------------------------
__device__ float g_h   [BT * DD];
__device__ float g_qkv [BT * 3 * DD];
__device__ float g_qr  [2 * 16 * 1024 * 64];
__device__ float g_kr  [2 * 16 * 1024 * 64];
__device__ float g_vb  [2 * 16 * 1024 * 64];
__device__ float g_o   [BT * DD];
__device__ float g_x2  [BT * DD];
__device__ float g_h2  [BT * DD];
__device__ float g_vv  [BT * DD];
__device__ float g_gates[(size_t)BT * NA];
__device__ float g_Apack[(size_t)2 * 64 * 1024 * 256];
__device__ float g_bv  [2 * 64 * 1024 * 16];
__device__ float g_hout[BT * DD];

// ---------------- RMSNorm ---------------------------------------------------
__global__ __launch_bounds__(256) void rmsnorm_kernel(
    const float* __restrict__ x, const float* __restrict__ w, float* __restrict__ out)
{
    int row = blockIdx.x;
    const float4* xr = (const float4*)(x + (size_t)row * DD);
    float4 xv = xr[threadIdx.x];
    float ss = xv.x*xv.x + xv.y*xv.y + xv.z*xv.z + xv.w*xv.w;
    #pragma unroll
    for (int o = 16; o > 0; o >>= 1) ss += __shfl_xor_sync(0xFFFFFFFFu, ss, o);
    __shared__ float red[8];
    if ((threadIdx.x & 31) == 0) red[threadIdx.x >> 5] = ss;
    __syncthreads();
    float tot = red[0]+red[1]+red[2]+red[3]+red[4]+red[5]+red[6]+red[7];
    float r = rsqrtf(tot * (1.0f/1024.0f) + 1e-5f);
    const float4* w4 = (const float4*)w;
    float4 wv = w4[threadIdx.x];
    float4 ov = make_float4(xv.x*r*wv.x, xv.y*r*wv.y, xv.z*r*wv.z, xv.w*r*wv.w);
    ((float4*)(out + (size_t)row * DD))[threadIdx.x] = ov;
}

// ---------------- TF32 tensor-core GEMM -------------------------------------
// C[M,N] = A[M,K] @ B[K,N] (+Cin). M%128==0, N%64==0, K%32==0.
// Block tile 128x64x32, 256 threads (8 warps as 4m x 2n, warp tile 32x32).
__device__ __forceinline__ unsigned f2tf(float f) {
    unsigned u;
    asm("cvt.rna.tf32.f32 %0, %1;" : "=r"(u) : "f"(f));
    return u;
}
__device__ __forceinline__ void mma_tf32(float* c, const unsigned* a, const unsigned* b) {
    asm volatile(
        "mma.sync.aligned.m16n8k8.row.col.f32.tf32.tf32.f32 "
        "{%0,%1,%2,%3}, {%4,%5,%6,%7}, {%8,%9}, {%0,%1,%2,%3};\n"
        : "+f"(c[0]), "+f"(c[1]), "+f"(c[2]), "+f"(c[3])
        : "r"(a[0]), "r"(a[1]), "r"(a[2]), "r"(a[3]), "r"(b[0]), "r"(b[1]));
}

#define TBM 128
#define TBN 64
#define TBK 32
#define APAD 132   // 128+4, bank-decorrelates fragment loads
#define BPAD 68    // 64+4

__global__ __launch_bounds__(256) void mma_gemm(
    const float* __restrict__ A, const float* __restrict__ B,
    const float* __restrict__ Cin, float* __restrict__ C,
    int Mm, int Nn, int Kk)
{
    __shared__ unsigned As[TBK][APAD];
    __shared__ unsigned Bs[TBK][BPAD];
    int tid = threadIdx.x;
    const int brow = blockIdx.y * TBM;
    const int bcol = blockIdx.x * TBN;

    int w   = tid >> 5;
    int wm  = w >> 1;           // 0..3 -> 32 rows each
    int wn  = w & 1;            // 0..1 -> 32 cols each
    int lane = tid & 31;
    int grp = lane >> 2;        // 0..7
    int qd  = lane & 3;         // 0..3

    float acc[8][4];
    #pragma unroll
    for (int i = 0; i < 8; i++)
        #pragma unroll
        for (int j = 0; j < 4; j++) acc[i][j] = 0.f;

    float4 pa[4], pb[2];
    // ---- load tile 0 into regs
    #pragma unroll
    for (int it = 0; it < 4; it++) {
        int idx = tid + it * 256;           // 0..1023
        int m = idx >> 3, kg = idx & 7;
        pa[it] = *(const float4*)(A + (size_t)(brow + m) * Kk + kg * 4);
    }
    #pragma unroll
    for (int it = 0; it < 2; it++) {
        int idx = tid + it * 256;           // 0..511
        int k = idx >> 4, n4 = (idx & 15) * 4;
        pb[it] = *(const float4*)(B + (size_t)k * Nn + bcol + n4);
    }
    // ---- store to smem
    #pragma unroll
    for (int it = 0; it < 4; it++) {
        int idx = tid + it * 256;
        int m = idx >> 3, kg = idx & 7;
        As[kg*4+0][m] = f2tf(pa[it].x);
        As[kg*4+1][m] = f2tf(pa[it].y);
        As[kg*4+2][m] = f2tf(pa[it].z);
        As[kg*4+3][m] = f2tf(pa[it].w);
    }
    #pragma unroll
    for (int it = 0; it < 2; it++) {
        int idx = tid + it * 256;
        int k = idx >> 4, n4 = (idx & 15) * 4;
        uint4 bv = make_uint4(f2tf(pb[it].x), f2tf(pb[it].y), f2tf(pb[it].z), f2tf(pb[it].w));
        *(uint4*)&Bs[k][n4] = bv;
    }
    __syncthreads();

    int ktiles = Kk / TBK;
    for (int kt = 0; kt < ktiles; kt++) {
        // ---- prefetch next tile into regs
        if (kt + 1 < ktiles) {
            int k0 = (kt + 1) * TBK;
            #pragma unroll
            for (int it = 0; it < 4; it++) {
                int idx = tid + it * 256;
                int m = idx >> 3, kg = idx & 7;
                pa[it] = *(const float4*)(A + (size_t)(brow + m) * Kk + k0 + kg * 4);
            }
            #pragma unroll
            for (int it = 0; it < 2; it++) {
                int idx = tid + it * 256;
                int k = idx >> 4, n4 = (idx & 15) * 4;
                pb[it] = *(const float4*)(B + (size_t)(k0 + k) * Nn + bcol + n4);
            }
        }
        // ---- compute 4 k-steps of 8
        #pragma unroll
        for (int ks = 0; ks < 4; ks++) {
            int kb = ks * 8;
            unsigned afr[2][4], bfr[4][2];
            #pragma unroll
            for (int i = 0; i < 2; i++) {
                int rr = wm * 32 + i * 16 + grp;
                afr[i][0] = As[kb + qd    ][rr];
                afr[i][1] = As[kb + qd    ][rr + 8];
                afr[i][2] = As[kb + qd + 4][rr];
                afr[i][3] = As[kb + qd + 4][rr + 8];
            }
            #pragma unroll
            for (int j = 0; j < 4; j++) {
                int nn = wn * 32 + j * 8 + grp;
                bfr[j][0] = Bs[kb + qd    ][nn];
                bfr[j][1] = Bs[kb + qd + 4][nn];
            }
            #pragma unroll
            for (int i = 0; i < 2; i++)
                #pragma unroll
                for (int j = 0; j < 4; j++)
                    mma_tf32(acc[i * 4 + j], afr[i], bfr[j]);
        }
        // ---- commit prefetched regs
        if (kt + 1 < ktiles) {
            __syncthreads();
            #pragma unroll
            for (int it = 0; it < 4; it++) {
                int idx = tid + it * 256;
                int m = idx >> 3, kg = idx & 7;
                As[kg*4+0][m] = f2tf(pa[it].x);
                As[kg*4+1][m] = f2tf(pa[it].y);
                As[kg*4+2][m] = f2tf(pa[it].z);
                As[kg*4+3][m] = f2tf(pa[it].w);
            }
            #pragma unroll
            for (int it = 0; it < 2; it++) {
                int idx = tid + it * 256;
                int k = idx >> 4, n4 = (idx & 15) * 4;
                uint4 bv = make_uint4(f2tf(pb[it].x), f2tf(pb[it].y), f2tf(pb[it].z), f2tf(pb[it].w));
                *(uint4*)&Bs[k][n4] = bv;
            }
            __syncthreads();
        }
    }

    // ---- epilogue
    #pragma unroll
    for (int i = 0; i < 2; i++) {
        #pragma unroll
        for (int j = 0; j < 4; j++) {
            size_t row0 = brow + wm * 32 + i * 16 + grp;
            size_t col  = bcol + wn * 32 + j * 8 + qd * 2;
            float2 v0 = make_float2(acc[i*4+j][0], acc[i*4+j][1]);
            float2 v1 = make_float2(acc[i*4+j][2], acc[i*4+j][3]);
            if (Cin) {
                float2 r0 = *(const float2*)(Cin + row0 * Nn + col);
                float2 r1 = *(const float2*)(Cin + (row0 + 8) * Nn + col);
                v0.x += r0.x; v0.y += r0.y; v1.x += r1.x; v1.y += r1.y;
            }
            *(float2*)(C + row0 * Nn + col) = v0;
            *(float2*)(C + (row0 + 8) * Nn + col) = v1;
        }
    }
}

// ---------------- RoPE + repack ---------------------------------------------
__global__ __launch_bounds__(256) void rope_kernel()
{
    int idx = blockIdx.x * 256 + threadIdx.x;
    int d  = idx & 63;
    int hh = (idx >> 6) & 15;
    int t  = (idx >> 10) & 1023;
    int b  = idx >> 20;
    const float* base = g_qkv + (size_t)(b * 1024 + t) * 3072;
    float qv = base[hh * 64 + d];
    float kv = base[1024 + hh * 64 + d];
    float vv = base[2048 + hh * 64 + d];
    int i = d & 31;
    float inv = powf(10000.0f, -(float)i * (1.0f / 32.0f));
    float f = (float)t * inv;
    float sn, cs;
    sincosf(f, &sn, &cs);
    float q2 = (d < 32) ? -base[hh*64 + d + 32] : base[hh*64 + d - 32];
    float k2 = (d < 32) ? -base[1024 + hh*64 + d + 32] : base[1024 + hh*64 + d - 32];
    size_t oi = ((size_t)(b * 16 + hh) * 1024 + t) * 64 + d;
    g_qr[oi] = qv * cs + q2 * sn;
    g_kr[oi] = kv * cs + k2 * sn;
    g_vb[oi] = vv;
}

// ---------------- Flash attention: 128 threads, lane-pair per q row ---------
__global__ __launch_bounds__(128) void attn_kernel()
{
    int bh = blockIdx.z * 16 + blockIdx.y;
    int q0 = blockIdx.x * 64;
    int tid = threadIdx.x;
    int row = tid >> 1;              // 0..63
    int half = tid & 1;              // interleaved dims: this thread owns 2d+half
    int t = q0 + row;

    const float* qrow = g_qr + ((size_t)bh * 1024 + t) * 64;
    float q[32];
    #pragma unroll
    for (int d = 0; d < 32; d++) q[d] = qrow[2*d + half];

    float m = -1e30f, l = 0.f;
    float oa[32];
    #pragma unroll
    for (int d = 0; d < 32; d++) oa[d] = 0.f;

    __shared__ float Ks[32][64];
    __shared__ float Vs[32][64];

    for (int s0 = 0; s0 < q0 + 64; s0 += 32) {
        for (int i = tid; i < 512; i += 128) {
            int r = i >> 4, c4 = (i & 15) * 4;
            *(float4*)&Ks[r][c4] = *(const float4*)(g_kr + ((size_t)bh*1024 + s0 + r)*64 + c4);
            *(float4*)&Vs[r][c4] = *(const float4*)(g_vb + ((size_t)bh*1024 + s0 + r)*64 + c4);
        }
        __syncthreads();
        float sc[32];
        float mt = m;
        #pragma unroll
        for (int j = 0; j < 32; j++) {
            float dot = 0.f;
            #pragma unroll
            for (int d = 0; d < 32; d++) dot = fmaf(q[d], Ks[j][2*d + half], dot);
            dot += __shfl_xor_sync(0xFFFFFFFFu, dot, 1);
            sc[j] = (s0 + j <= t) ? dot * 0.125f : -1e30f;
            mt = fmaxf(mt, sc[j]);
        }
        float corr = __expf(m - mt);
        l *= corr;
        #pragma unroll
        for (int d = 0; d < 32; d++) oa[d] *= corr;
        #pragma unroll
        for (int j = 0; j < 32; j++) {
            float p = __expf(sc[j] - mt);
            l += p;
            #pragma unroll
            for (int d = 0; d < 32; d++) oa[d] = fmaf(p, Vs[j][2*d + half], oa[d]);
        }
        m = mt;
        __syncthreads();
    }
    float inv = 1.0f / l;
    int b = bh >> 4, hh = bh & 15;
    float* orow = g_o + ((size_t)(b * 1024) + t) * 1024 + hh * 64;
    #pragma unroll
    for (int d = 0; d < 32; d++) orow[2*d + half] = oa[d] * inv;
}

// ---------------- gate softmax + pack ---------------------------------------
__global__ __launch_bounds__(256) void gate_pack_kernel()
{
    int idx = blockIdx.x * 256 + threadIdx.x;
    int mm = idx & 15;
    int hh = (idx >> 4) & 63;
    int t  = (idx >> 10) & 1023;
    int b  = idx >> 20;
    const float* g = g_gates + (size_t)idx * 17;
    float e[17];
    float mx = -1e30f;
    #pragma unroll
    for (int k = 0; k < 17; k++) { e[k] = g[k]; mx = fmaxf(mx, e[k]); }
    float sum = 0.f;
    #pragma unroll
    for (int k = 0; k < 17; k++) { e[k] = __expf(e[k] - mx); sum += e[k]; }
    float inv = 1.0f / sum;
    int bh = b * 64 + hh;
    float* Ad = g_Apack + (((size_t)bh * 1024 + t) * 16 + mm) * 16;
    #pragma unroll
    for (int k = 0; k < 16; k++) Ad[k] = e[k + 1] * inv;
    float v = g_vv[((size_t)(b * 1024 + t)) * 1024 + hh * 16 + mm];
    g_bv[((size_t)bh * 1024 + t) * 16 + mm] = e[0] * inv * v;
}

// ---------------- sequential gated scan -------------------------------------
__global__ __launch_bounds__(128) void scan_kernel()
{
    int bh = blockIdx.x;
    int b = bh >> 6, hh = bh & 63;
    __shared__ float Abuf[2][16 * 256];
    __shared__ float bvbuf[2][16 * 16];
    __shared__ float st[16];
    const float4* Ap = (const float4*)(g_Apack + (size_t)bh * 1024 * 256);
    const float4* Bp = (const float4*)(g_bv + (size_t)bh * 1024 * 16);
    int tid = threadIdx.x;
    if (tid < 16) st[tid] = 0.f;

    #pragma unroll
    for (int k = 0; k < 8; k++)
        ((float4*)Abuf[0])[tid + k * 128] = Ap[tid + k * 128];
    if (tid < 64) ((float4*)bvbuf[0])[tid] = Bp[tid];
    __syncthreads();

    int cur = 0;
    for (int c = 0; c < 64; c++) {
        float4 pf[8];
        float4 pb;
        if (c < 63) {
            #pragma unroll
            for (int k = 0; k < 8; k++)
                pf[k] = Ap[(size_t)(c + 1) * 1024 + tid + k * 128];
            if (tid < 64) pb = Bp[(size_t)(c + 1) * 64 + tid];
        }
        if (tid < 16) {
            const float4* Ab = (const float4*)Abuf[cur];
            const float* bvv = bvbuf[cur];
            float* hrow = g_hout + ((size_t)(b * 1024 + c * 16)) * 1024 + hh * 16 + tid;
            #pragma unroll 4
            for (int s = 0; s < 16; s++) {
                float4 s0 = *(const float4*)&st[0];
                float4 s1 = *(const float4*)&st[4];
                float4 s2 = *(const float4*)&st[8];
                float4 s3 = *(const float4*)&st[12];
                float4 a0 = Ab[s * 64 + tid * 4 + 0];
                float4 a1 = Ab[s * 64 + tid * 4 + 1];
                float4 a2 = Ab[s * 64 + tid * 4 + 2];
                float4 a3 = Ab[s * 64 + tid * 4 + 3];
                float p0 = fmaf(a0.x, s0.x, fmaf(a0.y, s0.y, fmaf(a0.z, s0.z, a0.w * s0.w)));
                float p1 = fmaf(a1.x, s1.x, fmaf(a1.y, s1.y, fmaf(a1.z, s1.z, a1.w * s1.w)));
                float p2 = fmaf(a2.x, s2.x, fmaf(a2.y, s2.y, fmaf(a2.z, s2.z, a2.w * s2.w)));
                float p3 = fmaf(a3.x, s3.x, fmaf(a3.y, s3.y, fmaf(a3.z, s3.z, a3.w * s3.w)));
                float acc = bvv[s * 16 + tid] + ((p0 + p1) + (p2 + p3));
                __syncwarp(0xFFFF);
                st[tid] = acc;
                __syncwarp(0xFFFF);
                hrow[(size_t)s * 1024] = acc;
            }
        }
        if (c < 63) {
            #pragma unroll
            for (int k = 0; k < 8; k++)
                ((float4*)Abuf[cur ^ 1])[tid + k * 128] = pf[k];
            if (tid < 64) ((float4*)bvbuf[cur ^ 1])[tid] = pb;
        }
        __syncthreads();
        cur ^= 1;
    }
}

// ---------------- launch ----------------------------------------------------
extern "C" void kernel_launch(void* const* d_in, const int* in_sizes, int n_in,
                              void* d_out, int out_size)
{
    const float* x    = (const float*)d_in[0];
    const float* anw  = (const float*)d_in[1];
    const float* wqkv = (const float*)d_in[2];
    const float* wao  = (const float*)d_in[3];
    const float* lnw  = (const float*)d_in[4];
    const float* wv   = (const float*)d_in[5];
    const float* wa   = (const float*)d_in[6];
    const float* wop  = (const float*)d_in[7];
    float* out = (float*)d_out;

    float *ph, *pqkv, *po, *px2, *ph2, *pvv, *pg, *phout;
    cudaGetSymbolAddress((void**)&ph,    g_h);
    cudaGetSymbolAddress((void**)&pqkv,  g_qkv);
    cudaGetSymbolAddress((void**)&po,    g_o);
    cudaGetSymbolAddress((void**)&px2,   g_x2);
    cudaGetSymbolAddress((void**)&ph2,   g_h2);
    cudaGetSymbolAddress((void**)&pvv,   g_vv);
    cudaGetSymbolAddress((void**)&pg,    g_gates);
    cudaGetSymbolAddress((void**)&phout, g_hout);

    rmsnorm_kernel<<<BT, 256>>>(x, anw, ph);
    mma_gemm<<<dim3(3072 / TBN, BT / TBM), 256>>>(ph, wqkv, nullptr, pqkv, BT, 3072, DD);
    rope_kernel<<<(2 * 1024 * 16 * 64) / 256, 256>>>();
    attn_kernel<<<dim3(16, 16, 2), 128>>>();
    mma_gemm<<<dim3(DD / TBN, BT / TBM), 256>>>(po, wao, x, px2, BT, DD, DD);
    rmsnorm_kernel<<<BT, 256>>>(px2, lnw, ph2);
    mma_gemm<<<dim3(DD / TBN, BT / TBM), 256>>>(ph2, wv, nullptr, pvv, BT, DD, DD);
    mma_gemm<<<dim3(NA / TBN, BT / TBM), 256>>>(ph2, wa, nullptr, pg, BT, NA, DD);
    gate_pack_kernel<<<(2 * 1024 * 64 * 16) / 256, 256>>>();
    scan_kernel<<<128, 128>>>();
    mma_gemm<<<dim3(DD / TBN, BT / TBM), 256>>>(phout, wop, px2, out, BT, DD, DD);
}

// round 4
// speedup vs baseline: 1.6338x; 1.0324x over previous
#include <cuda_runtime.h>
#include <math.h>
#include <stdint.h>

// B=2, T=1024, D=1024, NH=16, HD=64, H=64, M=16, N_a = H*M*(M+1) = 17408
#define BT 2048
#define DD 1024
#define NA 17408

// ---------------- scratch buffers -------------------------------------------
__device__ float g_h   [BT * DD];
__device__ float g_qkv [BT * 3 * DD];
__device__ float g_qr  [2 * 16 * 1024 * 64];
__device__ float g_kr  [2 * 16 * 1024 * 64];
__device__ float g_vb  [2 * 16 * 1024 * 64];
__device__ float g_o   [BT * DD];
__device__ float g_x2  [BT * DD];
__device__ float g_h2  [BT * DD];
__device__ float g_vv  [BT * DD];
__device__ float g_gates[(size_t)BT * NA];
__device__ float g_Apack[(size_t)2 * 64 * 1024 * 256];
__device__ float g_bv  [2 * 64 * 1024 * 16];
__device__ float g_hout[BT * DD];

// ---------------- mma / cp.async helpers ------------------------------------
__device__ __forceinline__ void mma_tf32(float* c, const uint32_t* a, const uint32_t* b) {
    asm volatile(
        "mma.sync.aligned.m16n8k8.row.col.f32.tf32.tf32.f32 "
        "{%0,%1,%2,%3}, {%4,%5,%6,%7}, {%8,%9}, {%0,%1,%2,%3};\n"
        : "+f"(c[0]), "+f"(c[1]), "+f"(c[2]), "+f"(c[3])
        : "r"(a[0]), "r"(a[1]), "r"(a[2]), "r"(a[3]), "r"(b[0]), "r"(b[1]));
}
__device__ __forceinline__ void cp_async16(uint32_t saddr, const void* gptr) {
    asm volatile("cp.async.cg.shared.global [%0], [%1], 16;" :: "r"(saddr), "l"(gptr));
}
#define CP_COMMIT() asm volatile("cp.async.commit_group;" ::: "memory")
#define CP_WAIT2()  asm volatile("cp.async.wait_group 2;" ::: "memory")
#define CP_WAIT0()  asm volatile("cp.async.wait_group 0;" ::: "memory")
__device__ __forceinline__ uint32_t smem_u32(const void* p) {
    uint32_t a;
    asm("{ .reg .u64 t; cvta.to.shared.u64 t, %1; cvt.u32.u64 %0, t; }"
        : "=r"(a) : "l"(p));
    return a;
}

// ---------------- RMSNorm ---------------------------------------------------
__global__ __launch_bounds__(256) void rmsnorm_kernel(
    const float* __restrict__ x, const float* __restrict__ w, float* __restrict__ out)
{
    int row = blockIdx.x;
    const float4* xr = (const float4*)(x + (size_t)row * DD);
    float4 xv = xr[threadIdx.x];
    float ss = xv.x*xv.x + xv.y*xv.y + xv.z*xv.z + xv.w*xv.w;
    #pragma unroll
    for (int o = 16; o > 0; o >>= 1) ss += __shfl_xor_sync(0xFFFFFFFFu, ss, o);
    __shared__ float red[8];
    if ((threadIdx.x & 31) == 0) red[threadIdx.x >> 5] = ss;
    __syncthreads();
    float tot = red[0]+red[1]+red[2]+red[3]+red[4]+red[5]+red[6]+red[7];
    float r = rsqrtf(tot * (1.0f/1024.0f) + 1e-5f);
    const float4* w4 = (const float4*)w;
    float4 wv = w4[threadIdx.x];
    float4 ov = make_float4(xv.x*r*wv.x, xv.y*r*wv.y, xv.z*r*wv.z, xv.w*r*wv.w);
    ((float4*)(out + (size_t)row * DD))[threadIdx.x] = ov;
}

// ---------------- TF32 mma.sync GEMM, 128x128x32, 3-stage cp.async ----------
// C[M,N] = A[M,K] @ B[K,N] (+Cin). M%128==0, N%128==0, K%32==0.
// 256 threads = 8 warps as 4(m) x 2(n); warp tile 32x64.
#define ASTRIDE 36
#define BSTRIDE 132
#define ABYTES (128 * ASTRIDE * 4)
#define STAGE_BYTES (ABYTES + 32 * BSTRIDE * 4)
#define GSM_TOT (3 * STAGE_BYTES)

__global__ __launch_bounds__(256) void tc_gemm(
    const float* __restrict__ A, const float* __restrict__ B,
    const float* __restrict__ Cin, float* __restrict__ C, int Nn, int Kk)
{
    extern __shared__ char smem[];
    float* sfp = (float*)smem;
    uint32_t sb = smem_u32(smem);
    int tid = threadIdx.x;
    const int brow = blockIdx.y * 128;
    const int bcol = blockIdx.x * 128;

    int w    = tid >> 5;
    int wm   = w >> 1;          // 0..3, 32 rows each
    int wn   = w & 1;           // 0..1, 64 cols each
    int lane = tid & 31;
    int grp  = lane >> 2;       // 0..7
    int qd   = lane & 3;        // 0..3

    float acc[2][8][4];
    #pragma unroll
    for (int i = 0; i < 2; i++)
        #pragma unroll
        for (int j = 0; j < 8; j++)
            #pragma unroll
            for (int q = 0; q < 4; q++) acc[i][j][q] = 0.f;

    // per-thread load coords (4 A chunks + 4 B chunks of 16B per stage)
    int a_row = tid >> 1;              // base rows: tid/2 + {0,64}? No: idx scheme below
    (void)a_row;

    const float* Ag = A + (size_t)brow * Kk;
    const int ktiles = Kk / 32;

    // issue cp.async for k-tile kt into stage s
    #define LOAD_TILE(kt, s) do {                                              \
        uint32_t ab = sb + (s) * STAGE_BYTES;                                  \
        uint32_t bb = ab + ABYTES;                                             \
        _Pragma("unroll")                                                      \
        for (int it = 0; it < 4; it++) {                                       \
            int idx = it * 256 + tid;       /* 0..1023 */                      \
            int r = idx >> 3, kq = idx & 7;                                    \
            cp_async16(ab + (uint32_t)(r * ASTRIDE + kq * 4) * 4,              \
                       Ag + (size_t)r * Kk + (kt) * 32 + kq * 4);              \
            int kr = idx >> 5, n4 = (idx & 31) * 4;                            \
            cp_async16(bb + (uint32_t)(kr * BSTRIDE + n4) * 4,                 \
                       B + (size_t)((kt) * 32 + kr) * Nn + bcol + n4);         \
        }                                                                      \
    } while (0)

    LOAD_TILE(0, 0); CP_COMMIT();
    if (ktiles > 1) { LOAD_TILE(1, 1); CP_COMMIT(); }
    else CP_COMMIT();

    for (int kt = 0; kt < ktiles; kt++) {
        int stg = kt - (kt / 3) * 3;
        if (kt + 2 < ktiles) {
            int s2 = (kt + 2) - ((kt + 2) / 3) * 3;
            LOAD_TILE(kt + 2, s2);
        }
        CP_COMMIT();
        CP_WAIT2();
        __syncthreads();

        const float* As = sfp + (size_t)stg * (STAGE_BYTES / 4);
        const float* Bs = As + ABYTES / 4;

        #pragma unroll
        for (int ks = 0; ks < 4; ks++) {
            int kb = ks * 8;
            uint32_t afr[2][4], bfr[8][2];
            #pragma unroll
            for (int i = 0; i < 2; i++) {
                int rr = wm * 32 + i * 16 + grp;
                afr[i][0] = __float_as_uint(As[rr * ASTRIDE + kb + qd]);
                afr[i][1] = __float_as_uint(As[(rr + 8) * ASTRIDE + kb + qd]);
                afr[i][2] = __float_as_uint(As[rr * ASTRIDE + kb + qd + 4]);
                afr[i][3] = __float_as_uint(As[(rr + 8) * ASTRIDE + kb + qd + 4]);
            }
            #pragma unroll
            for (int j = 0; j < 8; j++) {
                int nn = wn * 64 + j * 8 + grp;
                bfr[j][0] = __float_as_uint(Bs[(kb + qd) * BSTRIDE + nn]);
                bfr[j][1] = __float_as_uint(Bs[(kb + qd + 4) * BSTRIDE + nn]);
            }
            #pragma unroll
            for (int i = 0; i < 2; i++)
                #pragma unroll
                for (int j = 0; j < 8; j++)
                    mma_tf32(acc[i][j], afr[i], bfr[j]);
        }
        __syncthreads();
    }
    CP_WAIT0();

    // epilogue
    #pragma unroll
    for (int i = 0; i < 2; i++) {
        size_t row0 = (size_t)brow + wm * 32 + i * 16 + grp;
        #pragma unroll
        for (int j = 0; j < 8; j++) {
            size_t col = (size_t)bcol + wn * 64 + j * 8 + qd * 2;
            float2 v0 = make_float2(acc[i][j][0], acc[i][j][1]);
            float2 v1 = make_float2(acc[i][j][2], acc[i][j][3]);
            if (Cin) {
                float2 r0 = *(const float2*)(Cin + row0 * Nn + col);
                float2 r1 = *(const float2*)(Cin + (row0 + 8) * Nn + col);
                v0.x += r0.x; v0.y += r0.y; v1.x += r1.x; v1.y += r1.y;
            }
            *(float2*)(C + row0 * Nn + col) = v0;
            *(float2*)(C + (row0 + 8) * Nn + col) = v1;
        }
    }
    #undef LOAD_TILE
}

// ---------------- RoPE + repack ---------------------------------------------
__global__ __launch_bounds__(256) void rope_kernel()
{
    int idx = blockIdx.x * 256 + threadIdx.x;
    int d  = idx & 63;
    int hh = (idx >> 6) & 15;
    int t  = (idx >> 10) & 1023;
    int b  = idx >> 20;
    const float* base = g_qkv + (size_t)(b * 1024 + t) * 3072;
    float qv = base[hh * 64 + d];
    float kv = base[1024 + hh * 64 + d];
    float vv = base[2048 + hh * 64 + d];
    int i = d & 31;
    float inv = powf(10000.0f, -(float)i * (1.0f / 32.0f));
    float f = (float)t * inv;
    float sn, cs;
    sincosf(f, &sn, &cs);
    float q2 = (d < 32) ? -base[hh*64 + d + 32] : base[hh*64 + d - 32];
    float k2 = (d < 32) ? -base[1024 + hh*64 + d + 32] : base[1024 + hh*64 + d - 32];
    size_t oi = ((size_t)(b * 16 + hh) * 1024 + t) * 64 + d;
    g_qr[oi] = qv * cs + q2 * sn;
    g_kr[oi] = kv * cs + k2 * sn;
    g_vb[oi] = vv;
}

// ---------------- Flash attention (R1: 64 threads, 1 q-row/thread) ----------
__global__ __launch_bounds__(64) void attn_kernel()
{
    int bh = blockIdx.z * 16 + blockIdx.y;
    int q0 = blockIdx.x * 64;
    int t  = q0 + threadIdx.x;

    const float* qrow = g_qr + ((size_t)bh * 1024 + t) * 64;
    float q[64];
    #pragma unroll
    for (int d = 0; d < 64; d++) q[d] = qrow[d];

    float m = -1e30f, l = 0.f;
    float oa[64];
    #pragma unroll
    for (int d = 0; d < 64; d++) oa[d] = 0.f;

    __shared__ float Ks[32][64];
    __shared__ float Vs[32][64];

    for (int s0 = 0; s0 < q0 + 64; s0 += 32) {
        for (int i = threadIdx.x; i < 512; i += 64) {
            int r = i >> 4, c4 = (i & 15) * 4;
            *(float4*)&Ks[r][c4] = *(const float4*)(g_kr + ((size_t)bh*1024 + s0 + r)*64 + c4);
            *(float4*)&Vs[r][c4] = *(const float4*)(g_vb + ((size_t)bh*1024 + s0 + r)*64 + c4);
        }
        __syncthreads();
        float sc[32];
        float mt = m;
        #pragma unroll
        for (int j = 0; j < 32; j++) {
            float dot = 0.f;
            #pragma unroll
            for (int d = 0; d < 64; d++) dot = fmaf(q[d], Ks[j][d], dot);
            sc[j] = (s0 + j <= t) ? dot * 0.125f : -1e30f;
            mt = fmaxf(mt, sc[j]);
        }
        float corr = __expf(m - mt);
        l *= corr;
        #pragma unroll
        for (int d = 0; d < 64; d++) oa[d] *= corr;
        #pragma unroll
        for (int j = 0; j < 32; j++) {
            float p = __expf(sc[j] - mt);
            l += p;
            #pragma unroll
            for (int d = 0; d < 64; d++) oa[d] = fmaf(p, Vs[j][d], oa[d]);
        }
        m = mt;
        __syncthreads();
    }
    float inv = 1.0f / l;
    int b = bh >> 4, hh = bh & 15;
    float* orow = g_o + ((size_t)(b * 1024) + t) * 1024 + hh * 64;
    #pragma unroll
    for (int d = 0; d < 64; d++) orow[d] = oa[d] * inv;
}

// ---------------- gate softmax + pack ---------------------------------------
__global__ __launch_bounds__(256) void gate_pack_kernel()
{
    int idx = blockIdx.x * 256 + threadIdx.x;
    int mm = idx & 15;
    int hh = (idx >> 4) & 63;
    int t  = (idx >> 10) & 1023;
    int b  = idx >> 20;
    const float* g = g_gates + (size_t)idx * 17;
    float e[17];
    float mx = -1e30f;
    #pragma unroll
    for (int k = 0; k < 17; k++) { e[k] = g[k]; mx = fmaxf(mx, e[k]); }
    float sum = 0.f;
    #pragma unroll
    for (int k = 0; k < 17; k++) { e[k] = __expf(e[k] - mx); sum += e[k]; }
    float inv = 1.0f / sum;
    int bh = b * 64 + hh;
    float* Ad = g_Apack + (((size_t)bh * 1024 + t) * 16 + mm) * 16;
    #pragma unroll
    for (int k = 0; k < 16; k++) Ad[k] = e[k + 1] * inv;
    float v = g_vv[((size_t)(b * 1024 + t)) * 1024 + hh * 16 + mm];
    g_bv[((size_t)bh * 1024 + t) * 16 + mm] = e[0] * inv * v;
}

// ---------------- sequential gated scan -------------------------------------
__global__ __launch_bounds__(128) void scan_kernel()
{
    int bh = blockIdx.x;
    int b = bh >> 6, hh = bh & 63;
    __shared__ float Abuf[2][16 * 256];
    __shared__ float bvbuf[2][16 * 16];
    __shared__ float st[16];
    const float4* Ap = (const float4*)(g_Apack + (size_t)bh * 1024 * 256);
    const float4* Bp = (const float4*)(g_bv + (size_t)bh * 1024 * 16);
    int tid = threadIdx.x;
    if (tid < 16) st[tid] = 0.f;

    #pragma unroll
    for (int k = 0; k < 8; k++)
        ((float4*)Abuf[0])[tid + k * 128] = Ap[tid + k * 128];
    if (tid < 64) ((float4*)bvbuf[0])[tid] = Bp[tid];
    __syncthreads();

    int cur = 0;
    for (int c = 0; c < 64; c++) {
        float4 pf[8];
        float4 pb;
        if (c < 63) {
            #pragma unroll
            for (int k = 0; k < 8; k++)
                pf[k] = Ap[(size_t)(c + 1) * 1024 + tid + k * 128];
            if (tid < 64) pb = Bp[(size_t)(c + 1) * 64 + tid];
        }
        if (tid < 16) {
            const float4* Ab = (const float4*)Abuf[cur];
            const float* bvv = bvbuf[cur];
            float* hrow = g_hout + ((size_t)(b * 1024 + c * 16)) * 1024 + hh * 16 + tid;
            #pragma unroll 4
            for (int s = 0; s < 16; s++) {
                float4 s0 = *(const float4*)&st[0];
                float4 s1 = *(const float4*)&st[4];
                float4 s2 = *(const float4*)&st[8];
                float4 s3 = *(const float4*)&st[12];
                float4 a0 = Ab[s * 64 + tid * 4 + 0];
                float4 a1 = Ab[s * 64 + tid * 4 + 1];
                float4 a2 = Ab[s * 64 + tid * 4 + 2];
                float4 a3 = Ab[s * 64 + tid * 4 + 3];
                float p0 = fmaf(a0.x, s0.x, fmaf(a0.y, s0.y, fmaf(a0.z, s0.z, a0.w * s0.w)));
                float p1 = fmaf(a1.x, s1.x, fmaf(a1.y, s1.y, fmaf(a1.z, s1.z, a1.w * s1.w)));
                float p2 = fmaf(a2.x, s2.x, fmaf(a2.y, s2.y, fmaf(a2.z, s2.z, a2.w * s2.w)));
                float p3 = fmaf(a3.x, s3.x, fmaf(a3.y, s3.y, fmaf(a3.z, s3.z, a3.w * s3.w)));
                float acc = bvv[s * 16 + tid] + ((p0 + p1) + (p2 + p3));
                __syncwarp(0xFFFF);
                st[tid] = acc;
                __syncwarp(0xFFFF);
                hrow[(size_t)s * 1024] = acc;
            }
        }
        if (c < 63) {
            #pragma unroll
            for (int k = 0; k < 8; k++)
                ((float4*)Abuf[cur ^ 1])[tid + k * 128] = pf[k];
            if (tid < 64) ((float4*)bvbuf[cur ^ 1])[tid] = pb;
        }
        __syncthreads();
        cur ^= 1;
    }
}

// ---------------- launch ----------------------------------------------------
extern "C" void kernel_launch(void* const* d_in, const int* in_sizes, int n_in,
                              void* d_out, int out_size)
{
    const float* x    = (const float*)d_in[0];
    const float* anw  = (const float*)d_in[1];
    const float* wqkv = (const float*)d_in[2];
    const float* wao  = (const float*)d_in[3];
    const float* lnw  = (const float*)d_in[4];
    const float* wv   = (const float*)d_in[5];
    const float* wa   = (const float*)d_in[6];
    const float* wop  = (const float*)d_in[7];
    float* out = (float*)d_out;

    float *ph, *pqkv, *po, *px2, *ph2, *pvv, *pg, *phout;
    cudaGetSymbolAddress((void**)&ph,    g_h);
    cudaGetSymbolAddress((void**)&pqkv,  g_qkv);
    cudaGetSymbolAddress((void**)&po,    g_o);
    cudaGetSymbolAddress((void**)&px2,   g_x2);
    cudaGetSymbolAddress((void**)&ph2,   g_h2);
    cudaGetSymbolAddress((void**)&pvv,   g_vv);
    cudaGetSymbolAddress((void**)&pg,    g_gates);
    cudaGetSymbolAddress((void**)&phout, g_hout);

    cudaFuncSetAttribute(tc_gemm, cudaFuncAttributeMaxDynamicSharedMemorySize, GSM_TOT);

    rmsnorm_kernel<<<BT, 256>>>(x, anw, ph);
    tc_gemm<<<dim3(3072/128, BT/128), 256, GSM_TOT>>>(ph, wqkv, nullptr, pqkv, 3072, DD);
    rope_kernel<<<(2 * 1024 * 16 * 64) / 256, 256>>>();
    attn_kernel<<<dim3(16, 16, 2), 64>>>();
    tc_gemm<<<dim3(DD/128, BT/128), 256, GSM_TOT>>>(po, wao, x, px2, DD, DD);
    rmsnorm_kernel<<<BT, 256>>>(px2, lnw, ph2);
    tc_gemm<<<dim3(DD/128, BT/128), 256, GSM_TOT>>>(ph2, wv, nullptr, pvv, DD, DD);
    tc_gemm<<<dim3(NA/128, BT/128), 256, GSM_TOT>>>(ph2, wa, nullptr, pg, NA, DD);
    gate_pack_kernel<<<(2 * 1024 * 64 * 16) / 256, 256>>>();
    scan_kernel<<<128, 128>>>();
    tc_gemm<<<dim3(DD/128, BT/128), 256, GSM_TOT>>>(phout, wop, px2, out, DD, DD);
}

// round 5
// speedup vs baseline: 2.5653x; 1.5701x over previous
#include <cuda_runtime.h>
#include <math.h>
#include <stdint.h>

// B=2, T=1024, D=1024, NH=16, HD=64, H=64, M=16, N_a = H*M*(M+1) = 17408
#define BT 2048
#define DD 1024
#define NA 17408

// ---------------- scratch buffers -------------------------------------------
__device__ float g_h   [BT * DD];
__device__ float g_qkv [BT * 3 * DD];
__device__ float g_qr  [2 * 16 * 1024 * 64];
__device__ float g_kr  [2 * 16 * 1024 * 64];
__device__ float g_vb  [2 * 16 * 1024 * 64];
__device__ float g_o   [BT * DD];
__device__ float g_x2  [BT * DD];
__device__ float g_h2  [BT * DD];
__device__ float g_vv  [BT * DD];
__device__ float g_gates[(size_t)BT * NA];
__device__ float g_Apack[(size_t)2 * 64 * 1024 * 256];
__device__ float g_bv  [2 * 64 * 1024 * 16];
__device__ float g_hout[BT * DD];

// ---------------- mma / cp.async helpers ------------------------------------
__device__ __forceinline__ void mma_tf32(float* c, const uint32_t* a, const uint32_t* b) {
    asm volatile(
        "mma.sync.aligned.m16n8k8.row.col.f32.tf32.tf32.f32 "
        "{%0,%1,%2,%3}, {%4,%5,%6,%7}, {%8,%9}, {%0,%1,%2,%3};\n"
        : "+f"(c[0]), "+f"(c[1]), "+f"(c[2]), "+f"(c[3])
        : "r"(a[0]), "r"(a[1]), "r"(a[2]), "r"(a[3]), "r"(b[0]), "r"(b[1]));
}
__device__ __forceinline__ void cp_async16(uint32_t saddr, const void* gptr) {
    asm volatile("cp.async.cg.shared.global [%0], [%1], 16;" :: "r"(saddr), "l"(gptr));
}
#define CP_COMMIT() asm volatile("cp.async.commit_group;" ::: "memory")
#define CP_WAIT2()  asm volatile("cp.async.wait_group 2;" ::: "memory")
#define CP_WAIT1()  asm volatile("cp.async.wait_group 1;" ::: "memory")
#define CP_WAIT0()  asm volatile("cp.async.wait_group 0;" ::: "memory")
__device__ __forceinline__ uint32_t smem_u32(const void* p) {
    uint32_t a;
    asm("{ .reg .u64 t; cvta.to.shared.u64 t, %1; cvt.u32.u64 %0, t; }"
        : "=r"(a) : "l"(p));
    return a;
}

// ---------------- RMSNorm ---------------------------------------------------
__global__ __launch_bounds__(256) void rmsnorm_kernel(
    const float* __restrict__ x, const float* __restrict__ w, float* __restrict__ out)
{
    int row = blockIdx.x;
    const float4* xr = (const float4*)(x + (size_t)row * DD);
    float4 xv = xr[threadIdx.x];
    float ss = xv.x*xv.x + xv.y*xv.y + xv.z*xv.z + xv.w*xv.w;
    #pragma unroll
    for (int o = 16; o > 0; o >>= 1) ss += __shfl_xor_sync(0xFFFFFFFFu, ss, o);
    __shared__ float red[8];
    if ((threadIdx.x & 31) == 0) red[threadIdx.x >> 5] = ss;
    __syncthreads();
    float tot = red[0]+red[1]+red[2]+red[3]+red[4]+red[5]+red[6]+red[7];
    float r = rsqrtf(tot * (1.0f/1024.0f) + 1e-5f);
    const float4* w4 = (const float4*)w;
    float4 wv = w4[threadIdx.x];
    float4 ov = make_float4(xv.x*r*wv.x, xv.y*r*wv.y, xv.z*r*wv.z, xv.w*r*wv.w);
    ((float4*)(out + (size_t)row * DD))[threadIdx.x] = ov;
}

// ---------------- TF32 mma.sync GEMM, 128x128x32, 3-stage, 2 CTA/SM ---------
#define ASTRIDE 36
#define BSTRIDE 132
#define ABYTES (128 * ASTRIDE * 4)
#define STAGE_BYTES (ABYTES + 32 * BSTRIDE * 4)
#define GSM_TOT (3 * STAGE_BYTES)

__global__ __launch_bounds__(256, 2) void tc_gemm(
    const float* __restrict__ A, const float* __restrict__ B,
    const float* __restrict__ Cin, float* __restrict__ C, int Nn, int Kk)
{
    extern __shared__ char smem[];
    float* sfp = (float*)smem;
    uint32_t sb = smem_u32(smem);
    int tid = threadIdx.x;
    const int brow = blockIdx.y * 128;
    const int bcol = blockIdx.x * 128;

    int w    = tid >> 5;
    int wm   = w >> 1;          // 0..3, 32 rows each
    int wn   = w & 1;           // 0..1, 64 cols each
    int lane = tid & 31;
    int grp  = lane >> 2;       // 0..7
    int qd   = lane & 3;        // 0..3

    float acc[2][8][4];
    #pragma unroll
    for (int i = 0; i < 2; i++)
        #pragma unroll
        for (int j = 0; j < 8; j++)
            #pragma unroll
            for (int q = 0; q < 4; q++) acc[i][j][q] = 0.f;

    const float* Ag = A + (size_t)brow * Kk;
    const int ktiles = Kk / 32;

    #define LOAD_TILE(kt, s) do {                                              \
        uint32_t ab = sb + (s) * STAGE_BYTES;                                  \
        uint32_t bb = ab + ABYTES;                                             \
        _Pragma("unroll")                                                      \
        for (int it = 0; it < 4; it++) {                                       \
            int idx = it * 256 + tid;       /* 0..1023 */                      \
            int r = idx >> 3, kq = idx & 7;                                    \
            cp_async16(ab + (uint32_t)(r * ASTRIDE + kq * 4) * 4,              \
                       Ag + (size_t)r * Kk + (kt) * 32 + kq * 4);              \
            int kr = idx >> 5, n4 = (idx & 31) * 4;                            \
            cp_async16(bb + (uint32_t)(kr * BSTRIDE + n4) * 4,                 \
                       B + (size_t)((kt) * 32 + kr) * Nn + bcol + n4);         \
        }                                                                      \
        CP_COMMIT();                                                           \
    } while (0)

    LOAD_TILE(0, 0);
    if (ktiles > 1) LOAD_TILE(1, 1);

    for (int kt = 0; kt < ktiles; kt++) {
        int stg = kt - (kt / 3) * 3;
        if (kt + 2 < ktiles) {
            int s2 = (kt + 2) - ((kt + 2) / 3) * 3;
            LOAD_TILE(kt + 2, s2);
            CP_WAIT2();
        } else if (kt + 1 < ktiles) {
            CP_WAIT1();
        } else {
            CP_WAIT0();
        }
        __syncthreads();

        const float* As = sfp + (size_t)stg * (STAGE_BYTES / 4);
        const float* Bs = As + ABYTES / 4;

        #pragma unroll
        for (int ks = 0; ks < 4; ks++) {
            int kb = ks * 8;
            uint32_t afr[2][4], bfr[8][2];
            #pragma unroll
            for (int i = 0; i < 2; i++) {
                int rr = wm * 32 + i * 16 + grp;
                afr[i][0] = __float_as_uint(As[rr * ASTRIDE + kb + qd]);
                afr[i][1] = __float_as_uint(As[(rr + 8) * ASTRIDE + kb + qd]);
                afr[i][2] = __float_as_uint(As[rr * ASTRIDE + kb + qd + 4]);
                afr[i][3] = __float_as_uint(As[(rr + 8) * ASTRIDE + kb + qd + 4]);
            }
            #pragma unroll
            for (int j = 0; j < 8; j++) {
                int nn = wn * 64 + j * 8 + grp;
                bfr[j][0] = __float_as_uint(Bs[(kb + qd) * BSTRIDE + nn]);
                bfr[j][1] = __float_as_uint(Bs[(kb + qd + 4) * BSTRIDE + nn]);
            }
            #pragma unroll
            for (int i = 0; i < 2; i++)
                #pragma unroll
                for (int j = 0; j < 8; j++)
                    mma_tf32(acc[i][j], afr[i], bfr[j]);
        }
        __syncthreads();
    }

    // epilogue
    #pragma unroll
    for (int i = 0; i < 2; i++) {
        size_t row0 = (size_t)brow + wm * 32 + i * 16 + grp;
        #pragma unroll
        for (int j = 0; j < 8; j++) {
            size_t col = (size_t)bcol + wn * 64 + j * 8 + qd * 2;
            float2 v0 = make_float2(acc[i][j][0], acc[i][j][1]);
            float2 v1 = make_float2(acc[i][j][2], acc[i][j][3]);
            if (Cin) {
                float2 r0 = *(const float2*)(Cin + row0 * Nn + col);
                float2 r1 = *(const float2*)(Cin + (row0 + 8) * Nn + col);
                v0.x += r0.x; v0.y += r0.y; v1.x += r1.x; v1.y += r1.y;
            }
            *(float2*)(C + row0 * Nn + col) = v0;
            *(float2*)(C + (row0 + 8) * Nn + col) = v1;
        }
    }
    #undef LOAD_TILE
}

// ---------------- RoPE + repack ---------------------------------------------
__global__ __launch_bounds__(256) void rope_kernel()
{
    int idx = blockIdx.x * 256 + threadIdx.x;
    int d  = idx & 63;
    int hh = (idx >> 6) & 15;
    int t  = (idx >> 10) & 1023;
    int b  = idx >> 20;
    const float* base = g_qkv + (size_t)(b * 1024 + t) * 3072;
    float qv = base[hh * 64 + d];
    float kv = base[1024 + hh * 64 + d];
    float vv = base[2048 + hh * 64 + d];
    int i = d & 31;
    // 10000^(-i/32) = 2^(-i*log2(10000)/32)
    float inv = exp2f((float)i * (-13.287712379549449f / 32.0f));
    float f = (float)t * inv;
    float sn, cs;
    sincosf(f, &sn, &cs);
    float q2 = (d < 32) ? -base[hh*64 + d + 32] : base[hh*64 + d - 32];
    float k2 = (d < 32) ? -base[1024 + hh*64 + d + 32] : base[1024 + hh*64 + d - 32];
    size_t oi = ((size_t)(b * 16 + hh) * 1024 + t) * 64 + d;
    g_qr[oi] = qv * cs + q2 * sn;
    g_kr[oi] = kv * cs + k2 * sn;
    g_vb[oi] = vv;
}

// ---------------- Flash attention: 128 q-rows/block, float4 smem reads ------
__global__ __launch_bounds__(128) void attn_kernel()
{
    int bh = blockIdx.z * 16 + blockIdx.y;
    int q0 = blockIdx.x * 128;
    int tid = threadIdx.x;
    int t = q0 + tid;

    const float4* q4p = (const float4*)(g_qr + ((size_t)bh * 1024 + t) * 64);
    float4 q[16];
    #pragma unroll
    for (int d = 0; d < 16; d++) q[d] = q4p[d];

    float m = -1e30f, l = 0.f;
    float4 oa[16];
    #pragma unroll
    for (int d = 0; d < 16; d++) oa[d] = make_float4(0.f, 0.f, 0.f, 0.f);

    __shared__ float Ks[32][64];
    __shared__ float Vs[32][64];

    for (int s0 = 0; s0 < q0 + 128; s0 += 32) {
        #pragma unroll
        for (int i = tid; i < 512; i += 128) {
            int r = i >> 4, c4 = (i & 15) * 4;
            *(float4*)&Ks[r][c4] = *(const float4*)(g_kr + ((size_t)bh*1024 + s0 + r)*64 + c4);
            *(float4*)&Vs[r][c4] = *(const float4*)(g_vb + ((size_t)bh*1024 + s0 + r)*64 + c4);
        }
        __syncthreads();
        float sc[32];
        float mt = m;
        #pragma unroll
        for (int j = 0; j < 32; j++) {
            const float4* K4 = (const float4*)&Ks[j][0];
            float dot = 0.f;
            #pragma unroll
            for (int d = 0; d < 16; d++) {
                float4 kv = K4[d];
                dot = fmaf(q[d].x, kv.x, dot);
                dot = fmaf(q[d].y, kv.y, dot);
                dot = fmaf(q[d].z, kv.z, dot);
                dot = fmaf(q[d].w, kv.w, dot);
            }
            sc[j] = (s0 + j <= t) ? dot * 0.125f : -1e30f;
            mt = fmaxf(mt, sc[j]);
        }
        float corr = __expf(m - mt);
        l *= corr;
        #pragma unroll
        for (int d = 0; d < 16; d++) {
            oa[d].x *= corr; oa[d].y *= corr; oa[d].z *= corr; oa[d].w *= corr;
        }
        #pragma unroll
        for (int j = 0; j < 32; j++) {
            float p = __expf(sc[j] - mt);
            l += p;
            const float4* V4 = (const float4*)&Vs[j][0];
            #pragma unroll
            for (int d = 0; d < 16; d++) {
                float4 vv = V4[d];
                oa[d].x = fmaf(p, vv.x, oa[d].x);
                oa[d].y = fmaf(p, vv.y, oa[d].y);
                oa[d].z = fmaf(p, vv.z, oa[d].z);
                oa[d].w = fmaf(p, vv.w, oa[d].w);
            }
        }
        m = mt;
        __syncthreads();
    }
    float inv = 1.0f / l;
    int b = bh >> 4, hh = bh & 15;
    float4* orow = (float4*)(g_o + ((size_t)(b * 1024) + t) * 1024 + hh * 64);
    #pragma unroll
    for (int d = 0; d < 16; d++) {
        float4 v = make_float4(oa[d].x * inv, oa[d].y * inv, oa[d].z * inv, oa[d].w * inv);
        orow[d] = v;
    }
}

// ---------------- gate softmax + pack ---------------------------------------
__global__ __launch_bounds__(256) void gate_pack_kernel()
{
    int idx = blockIdx.x * 256 + threadIdx.x;
    int mm = idx & 15;
    int hh = (idx >> 4) & 63;
    int t  = (idx >> 10) & 1023;
    int b  = idx >> 20;
    const float* g = g_gates + (size_t)idx * 17;
    float e[17];
    float mx = -1e30f;
    #pragma unroll
    for (int k = 0; k < 17; k++) { e[k] = g[k]; mx = fmaxf(mx, e[k]); }
    float sum = 0.f;
    #pragma unroll
    for (int k = 0; k < 17; k++) { e[k] = __expf(e[k] - mx); sum += e[k]; }
    float inv = 1.0f / sum;
    int bh = b * 64 + hh;
    float* Ad = g_Apack + (((size_t)bh * 1024 + t) * 16 + mm) * 16;
    #pragma unroll
    for (int k = 0; k < 16; k++) Ad[k] = e[k + 1] * inv;
    float v = g_vv[((size_t)(b * 1024 + t)) * 1024 + hh * 16 + mm];
    g_bv[((size_t)bh * 1024 + t) * 16 + mm] = e[0] * inv * v;
}

// ---------------- sequential gated scan -------------------------------------
__global__ __launch_bounds__(128) void scan_kernel()
{
    int bh = blockIdx.x;
    int b = bh >> 6, hh = bh & 63;
    __shared__ float Abuf[2][16 * 256];
    __shared__ float bvbuf[2][16 * 16];
    __shared__ float st[16];
    const float4* Ap = (const float4*)(g_Apack + (size_t)bh * 1024 * 256);
    const float4* Bp = (const float4*)(g_bv + (size_t)bh * 1024 * 16);
    int tid = threadIdx.x;
    if (tid < 16) st[tid] = 0.f;

    #pragma unroll
    for (int k = 0; k < 8; k++)
        ((float4*)Abuf[0])[tid + k * 128] = Ap[tid + k * 128];
    if (tid < 64) ((float4*)bvbuf[0])[tid] = Bp[tid];
    __syncthreads();

    int cur = 0;
    for (int c = 0; c < 64; c++) {
        float4 pf[8];
        float4 pb;
        if (c < 63) {
            #pragma unroll
            for (int k = 0; k < 8; k++)
                pf[k] = Ap[(size_t)(c + 1) * 1024 + tid + k * 128];
            if (tid < 64) pb = Bp[(size_t)(c + 1) * 64 + tid];
        }
        if (tid < 16) {
            const float4* Ab = (const float4*)Abuf[cur];
            const float* bvv = bvbuf[cur];
            float* hrow = g_hout + ((size_t)(b * 1024 + c * 16)) * 1024 + hh * 16 + tid;
            #pragma unroll 4
            for (int s = 0; s < 16; s++) {
                float4 s0 = *(const float4*)&st[0];
                float4 s1 = *(const float4*)&st[4];
                float4 s2 = *(const float4*)&st[8];
                float4 s3 = *(const float4*)&st[12];
                float4 a0 = Ab[s * 64 + tid * 4 + 0];
                float4 a1 = Ab[s * 64 + tid * 4 + 1];
                float4 a2 = Ab[s * 64 + tid * 4 + 2];
                float4 a3 = Ab[s * 64 + tid * 4 + 3];
                float p0 = fmaf(a0.x, s0.x, fmaf(a0.y, s0.y, fmaf(a0.z, s0.z, a0.w * s0.w)));
                float p1 = fmaf(a1.x, s1.x, fmaf(a1.y, s1.y, fmaf(a1.z, s1.z, a1.w * s1.w)));
                float p2 = fmaf(a2.x, s2.x, fmaf(a2.y, s2.y, fmaf(a2.z, s2.z, a2.w * s2.w)));
                float p3 = fmaf(a3.x, s3.x, fmaf(a3.y, s3.y, fmaf(a3.z, s3.z, a3.w * s3.w)));
                float acc = bvv[s * 16 + tid] + ((p0 + p1) + (p2 + p3));
                __syncwarp(0xFFFF);
                st[tid] = acc;
                __syncwarp(0xFFFF);
                hrow[(size_t)s * 1024] = acc;
            }
        }
        if (c < 63) {
            #pragma unroll
            for (int k = 0; k < 8; k++)
                ((float4*)Abuf[cur ^ 1])[tid + k * 128] = pf[k];
            if (tid < 64) ((float4*)bvbuf[cur ^ 1])[tid] = pb;
        }
        __syncthreads();
        cur ^= 1;
    }
}

// ---------------- launch ----------------------------------------------------
extern "C" void kernel_launch(void* const* d_in, const int* in_sizes, int n_in,
                              void* d_out, int out_size)
{
    const float* x    = (const float*)d_in[0];
    const float* anw  = (const float*)d_in[1];
    const float* wqkv = (const float*)d_in[2];
    const float* wao  = (const float*)d_in[3];
    const float* lnw  = (const float*)d_in[4];
    const float* wv   = (const float*)d_in[5];
    const float* wa   = (const float*)d_in[6];
    const float* wop  = (const float*)d_in[7];
    float* out = (float*)d_out;

    float *ph, *pqkv, *po, *px2, *ph2, *pvv, *pg, *phout;
    cudaGetSymbolAddress((void**)&ph,    g_h);
    cudaGetSymbolAddress((void**)&pqkv,  g_qkv);
    cudaGetSymbolAddress((void**)&po,    g_o);
    cudaGetSymbolAddress((void**)&px2,   g_x2);
    cudaGetSymbolAddress((void**)&ph2,   g_h2);
    cudaGetSymbolAddress((void**)&pvv,   g_vv);
    cudaGetSymbolAddress((void**)&pg,    g_gates);
    cudaGetSymbolAddress((void**)&phout, g_hout);

    cudaFuncSetAttribute(tc_gemm, cudaFuncAttributeMaxDynamicSharedMemorySize, GSM_TOT);

    rmsnorm_kernel<<<BT, 256>>>(x, anw, ph);
    tc_gemm<<<dim3(3072/128, BT/128), 256, GSM_TOT>>>(ph, wqkv, nullptr, pqkv, 3072, DD);
    rope_kernel<<<(2 * 1024 * 16 * 64) / 256, 256>>>();
    attn_kernel<<<dim3(8, 16, 2), 128>>>();
    tc_gemm<<<dim3(DD/128, BT/128), 256, GSM_TOT>>>(po, wao, x, px2, DD, DD);
    rmsnorm_kernel<<<BT, 256>>>(px2, lnw, ph2);
    tc_gemm<<<dim3(DD/128, BT/128), 256, GSM_TOT>>>(ph2, wv, nullptr, pvv, DD, DD);
    tc_gemm<<<dim3(NA/128, BT/128), 256, GSM_TOT>>>(ph2, wa, nullptr, pg, NA, DD);
    gate_pack_kernel<<<(2 * 1024 * 64 * 16) / 256, 256>>>();
    scan_kernel<<<128, 128>>>();
    tc_gemm<<<dim3(DD/128, BT/128), 256, GSM_TOT>>>(phout, wop, px2, out, DD, DD);
}

// round 6
// speedup vs baseline: 3.1358x; 1.2224x over previous
#include <cuda_runtime.h>
#include <math.h>
#include <stdint.h>

// B=2, T=1024, D=1024, NH=16, HD=64, H=64, M=16, N_a = H*M*(M+1) = 17408
#define BT 2048
#define DD 1024
#define NA 17408

// ---------------- scratch buffers -------------------------------------------
__device__ float g_h   [BT * DD];
__device__ float g_qkv [BT * 3 * DD];
__device__ float g_qr  [2 * 16 * 1024 * 64];
__device__ float g_kr  [2 * 16 * 1024 * 64];
__device__ float g_vb  [2 * 16 * 1024 * 64];
__device__ float g_o   [BT * DD];
__device__ float g_x2  [BT * DD];
__device__ float g_h2  [BT * DD];
__device__ float g_vv  [BT * DD];
__device__ float g_gates[(size_t)BT * NA];
__device__ float g_Apack[(size_t)2 * 64 * 1024 * 256];
__device__ float g_bv  [2 * 64 * 1024 * 16];
__device__ float g_hout[BT * DD];

// ---------------- mma / cp.async helpers ------------------------------------
__device__ __forceinline__ void mma_tf32(float* c, const uint32_t* a, const uint32_t* b) {
    asm volatile(
        "mma.sync.aligned.m16n8k8.row.col.f32.tf32.tf32.f32 "
        "{%0,%1,%2,%3}, {%4,%5,%6,%7}, {%8,%9}, {%0,%1,%2,%3};\n"
        : "+f"(c[0]), "+f"(c[1]), "+f"(c[2]), "+f"(c[3])
        : "r"(a[0]), "r"(a[1]), "r"(a[2]), "r"(a[3]), "r"(b[0]), "r"(b[1]));
}
__device__ __forceinline__ void cp_async16(uint32_t saddr, const void* gptr) {
    asm volatile("cp.async.cg.shared.global [%0], [%1], 16;" :: "r"(saddr), "l"(gptr));
}
#define CP_COMMIT() asm volatile("cp.async.commit_group;" ::: "memory")
#define CP_WAIT2()  asm volatile("cp.async.wait_group 2;" ::: "memory")
#define CP_WAIT1()  asm volatile("cp.async.wait_group 1;" ::: "memory")
#define CP_WAIT0()  asm volatile("cp.async.wait_group 0;" ::: "memory")
__device__ __forceinline__ uint32_t smem_u32(const void* p) {
    uint32_t a;
    asm("{ .reg .u64 t; cvta.to.shared.u64 t, %1; cvt.u32.u64 %0, t; }"
        : "=r"(a) : "l"(p));
    return a;
}

// ---------------- RMSNorm ---------------------------------------------------
__global__ __launch_bounds__(256) void rmsnorm_kernel(
    const float* __restrict__ x, const float* __restrict__ w, float* __restrict__ out)
{
    int row = blockIdx.x;
    const float4* xr = (const float4*)(x + (size_t)row * DD);
    float4 xv = xr[threadIdx.x];
    float ss = xv.x*xv.x + xv.y*xv.y + xv.z*xv.z + xv.w*xv.w;
    #pragma unroll
    for (int o = 16; o > 0; o >>= 1) ss += __shfl_xor_sync(0xFFFFFFFFu, ss, o);
    __shared__ float red[8];
    if ((threadIdx.x & 31) == 0) red[threadIdx.x >> 5] = ss;
    __syncthreads();
    float tot = red[0]+red[1]+red[2]+red[3]+red[4]+red[5]+red[6]+red[7];
    float r = rsqrtf(tot * (1.0f/1024.0f) + 1e-5f);
    const float4* w4 = (const float4*)w;
    float4 wv = w4[threadIdx.x];
    float4 ov = make_float4(xv.x*r*wv.x, xv.y*r*wv.y, xv.z*r*wv.z, xv.w*r*wv.w);
    ((float4*)(out + (size_t)row * DD))[threadIdx.x] = ov;
}

// ---------------- TF32 mma.sync GEMM, 128x128x32, 3-stage, 2 CTA/SM ---------
#define ASTRIDE 36
#define BSTRIDE 132
#define ABYTES (128 * ASTRIDE * 4)
#define STAGE_BYTES (ABYTES + 32 * BSTRIDE * 4)
#define GSM_TOT (3 * STAGE_BYTES)

__global__ __launch_bounds__(256, 2) void tc_gemm(
    const float* __restrict__ A, const float* __restrict__ B,
    const float* __restrict__ Cin, float* __restrict__ C, int Nn, int Kk)
{
    extern __shared__ char smem[];
    float* sfp = (float*)smem;
    uint32_t sb = smem_u32(smem);
    int tid = threadIdx.x;
    const int brow = blockIdx.y * 128;
    const int bcol = blockIdx.x * 128;

    int w    = tid >> 5;
    int wm   = w >> 1;
    int wn   = w & 1;
    int lane = tid & 31;
    int grp  = lane >> 2;
    int qd   = lane & 3;

    float acc[2][8][4];
    #pragma unroll
    for (int i = 0; i < 2; i++)
        #pragma unroll
        for (int j = 0; j < 8; j++)
            #pragma unroll
            for (int q = 0; q < 4; q++) acc[i][j][q] = 0.f;

    const float* Ag = A + (size_t)brow * Kk;
    const int ktiles = Kk / 32;

    #define LOAD_TILE(kt, s) do {                                              \
        uint32_t ab = sb + (s) * STAGE_BYTES;                                  \
        uint32_t bb = ab + ABYTES;                                             \
        _Pragma("unroll")                                                      \
        for (int it = 0; it < 4; it++) {                                       \
            int idx = it * 256 + tid;                                          \
            int r = idx >> 3, kq = idx & 7;                                    \
            cp_async16(ab + (uint32_t)(r * ASTRIDE + kq * 4) * 4,              \
                       Ag + (size_t)r * Kk + (kt) * 32 + kq * 4);              \
            int kr = idx >> 5, n4 = (idx & 31) * 4;                            \
            cp_async16(bb + (uint32_t)(kr * BSTRIDE + n4) * 4,                 \
                       B + (size_t)((kt) * 32 + kr) * Nn + bcol + n4);         \
        }                                                                      \
        CP_COMMIT();                                                           \
    } while (0)

    LOAD_TILE(0, 0);
    if (ktiles > 1) LOAD_TILE(1, 1);

    for (int kt = 0; kt < ktiles; kt++) {
        int stg = kt - (kt / 3) * 3;
        if (kt + 2 < ktiles) {
            int s2 = (kt + 2) - ((kt + 2) / 3) * 3;
            LOAD_TILE(kt + 2, s2);
            CP_WAIT2();
        } else if (kt + 1 < ktiles) {
            CP_WAIT1();
        } else {
            CP_WAIT0();
        }
        __syncthreads();

        const float* As = sfp + (size_t)stg * (STAGE_BYTES / 4);
        const float* Bs = As + ABYTES / 4;

        #pragma unroll
        for (int ks = 0; ks < 4; ks++) {
            int kb = ks * 8;
            uint32_t afr[2][4], bfr[8][2];
            #pragma unroll
            for (int i = 0; i < 2; i++) {
                int rr = wm * 32 + i * 16 + grp;
                afr[i][0] = __float_as_uint(As[rr * ASTRIDE + kb + qd]);
                afr[i][1] = __float_as_uint(As[(rr + 8) * ASTRIDE + kb + qd]);
                afr[i][2] = __float_as_uint(As[rr * ASTRIDE + kb + qd + 4]);
                afr[i][3] = __float_as_uint(As[(rr + 8) * ASTRIDE + kb + qd + 4]);
            }
            #pragma unroll
            for (int j = 0; j < 8; j++) {
                int nn = wn * 64 + j * 8 + grp;
                bfr[j][0] = __float_as_uint(Bs[(kb + qd) * BSTRIDE + nn]);
                bfr[j][1] = __float_as_uint(Bs[(kb + qd + 4) * BSTRIDE + nn]);
            }
            #pragma unroll
            for (int i = 0; i < 2; i++)
                #pragma unroll
                for (int j = 0; j < 8; j++)
                    mma_tf32(acc[i][j], afr[i], bfr[j]);
        }
        __syncthreads();
    }

    #pragma unroll
    for (int i = 0; i < 2; i++) {
        size_t row0 = (size_t)brow + wm * 32 + i * 16 + grp;
        #pragma unroll
        for (int j = 0; j < 8; j++) {
            size_t col = (size_t)bcol + wn * 64 + j * 8 + qd * 2;
            float2 v0 = make_float2(acc[i][j][0], acc[i][j][1]);
            float2 v1 = make_float2(acc[i][j][2], acc[i][j][3]);
            if (Cin) {
                float2 r0 = *(const float2*)(Cin + row0 * Nn + col);
                float2 r1 = *(const float2*)(Cin + (row0 + 8) * Nn + col);
                v0.x += r0.x; v0.y += r0.y; v1.x += r1.x; v1.y += r1.y;
            }
            *(float2*)(C + row0 * Nn + col) = v0;
            *(float2*)(C + (row0 + 8) * Nn + col) = v1;
        }
    }
    #undef LOAD_TILE
}

// ---------------- RoPE + repack ---------------------------------------------
__global__ __launch_bounds__(256) void rope_kernel()
{
    int idx = blockIdx.x * 256 + threadIdx.x;
    int d  = idx & 63;
    int hh = (idx >> 6) & 15;
    int t  = (idx >> 10) & 1023;
    int b  = idx >> 20;
    const float* base = g_qkv + (size_t)(b * 1024 + t) * 3072;
    float qv = base[hh * 64 + d];
    float kv = base[1024 + hh * 64 + d];
    float vv = base[2048 + hh * 64 + d];
    int i = d & 31;
    float inv = exp2f((float)i * (-13.287712379549449f / 32.0f));
    float f = (float)t * inv;
    float sn, cs;
    sincosf(f, &sn, &cs);
    float q2 = (d < 32) ? -base[hh*64 + d + 32] : base[hh*64 + d - 32];
    float k2 = (d < 32) ? -base[1024 + hh*64 + d + 32] : base[1024 + hh*64 + d - 32];
    size_t oi = ((size_t)(b * 16 + hh) * 1024 + t) * 64 + d;
    g_qr[oi] = qv * cs + q2 * sn;
    g_kr[oi] = kv * cs + k2 * sn;
    g_vb[oi] = vv;
}

// ---------------- Tensor-core flash attention --------------------------------
// Block: 64 q rows, 4 warps (16 rows/warp), KV tiles of 64, tf32 mma.
// Smem: QP buf 64x72 (Q, then per-warp-exclusive P), Ks 64x72, Vs 64x72.
#define ATS 72
#define ATT_SMEM (3 * 64 * ATS * 4)

__global__ __launch_bounds__(128) void attn_tc_kernel()
{
    extern __shared__ float s[];
    float* QP = s;                  // Q tile, later P tile (warp-exclusive rows)
    float* Ks = s + 64 * ATS;
    float* Vs = s + 2 * 64 * ATS;

    int bh = blockIdx.z * 16 + blockIdx.y;
    int q0 = blockIdx.x * 64;
    int tid = threadIdx.x;
    int w = tid >> 5, lane = tid & 31;
    int grp = lane >> 2, qd = lane & 3;
    int rr = w * 16 + grp;          // warp-local output rows rr, rr+8

    // ---- load Q tile (64x64) into smem
    const float* Qg = g_qr + ((size_t)bh * 1024 + q0) * 64;
    #pragma unroll
    for (int it = 0; it < 8; it++) {
        int i = it * 128 + tid;
        int r = i >> 4, c = (i & 15) * 4;
        *(float4*)&QP[r * ATS + c] = *(const float4*)(Qg + (size_t)r * 64 + c);
    }
    __syncthreads();

    // ---- build persistent Q fragments (A-layout), rows rr/rr+8
    uint32_t qfr[8][4];
    #pragma unroll
    for (int k = 0; k < 8; k++) {
        qfr[k][0] = __float_as_uint(QP[rr * ATS + k * 8 + qd]);
        qfr[k][1] = __float_as_uint(QP[(rr + 8) * ATS + k * 8 + qd]);
        qfr[k][2] = __float_as_uint(QP[rr * ATS + k * 8 + qd + 4]);
        qfr[k][3] = __float_as_uint(QP[(rr + 8) * ATS + k * 8 + qd + 4]);
    }

    float m0 = -1e30f, m1 = -1e30f, l0 = 0.f, l1 = 0.f;
    float o[8][4];
    #pragma unroll
    for (int j = 0; j < 8; j++)
        #pragma unroll
        for (int q = 0; q < 4; q++) o[j][q] = 0.f;

    int row_g0 = q0 + rr;           // global query indices for mask
    int row_g1 = row_g0 + 8;

    int ntiles = q0 / 64 + 1;
    for (int tIdx = 0; tIdx < ntiles; tIdx++) {
        int s0 = tIdx * 64;
        __syncthreads();            // protect K/V from previous-tile readers
        const float* Kg = g_kr + ((size_t)bh * 1024 + s0) * 64;
        const float* Vg = g_vb + ((size_t)bh * 1024 + s0) * 64;
        #pragma unroll
        for (int it = 0; it < 8; it++) {
            int i = it * 128 + tid;
            int r = i >> 4, c = (i & 15) * 4;
            *(float4*)&Ks[r * ATS + c] = *(const float4*)(Kg + (size_t)r * 64 + c);
            *(float4*)&Vs[r * ATS + c] = *(const float4*)(Vg + (size_t)r * 64 + c);
        }
        __syncthreads();

        // ---- scores = Q @ K^T  (B-frag read from K rows: B[k][n] = Ks[n][k])
        float sc[8][4];
        #pragma unroll
        for (int j = 0; j < 8; j++)
            #pragma unroll
            for (int q = 0; q < 4; q++) sc[j][q] = 0.f;
        #pragma unroll
        for (int k = 0; k < 8; k++) {
            int kb = k * 8;
            uint32_t bfr[8][2];
            #pragma unroll
            for (int nt = 0; nt < 8; nt++) {
                int nn = nt * 8 + grp;
                bfr[nt][0] = __float_as_uint(Ks[nn * ATS + kb + qd]);
                bfr[nt][1] = __float_as_uint(Ks[nn * ATS + kb + qd + 4]);
            }
            #pragma unroll
            for (int nt = 0; nt < 8; nt++)
                mma_tf32(sc[nt], qfr[k], bfr[nt]);
        }

        // ---- scale + causal mask (diagonal tile only)
        bool diag = (s0 == q0);
        #pragma unroll
        for (int nt = 0; nt < 8; nt++) {
            int c0 = s0 + nt * 8 + 2 * qd;
            sc[nt][0] *= 0.125f; sc[nt][1] *= 0.125f;
            sc[nt][2] *= 0.125f; sc[nt][3] *= 0.125f;
            if (diag) {
                if (c0 > row_g0)     sc[nt][0] = -1e30f;
                if (c0 + 1 > row_g0) sc[nt][1] = -1e30f;
                if (c0 > row_g1)     sc[nt][2] = -1e30f;
                if (c0 + 1 > row_g1) sc[nt][3] = -1e30f;
            }
        }

        // ---- online softmax on fragments
        float mt0 = -1e30f, mt1 = -1e30f;
        #pragma unroll
        for (int nt = 0; nt < 8; nt++) {
            mt0 = fmaxf(mt0, fmaxf(sc[nt][0], sc[nt][1]));
            mt1 = fmaxf(mt1, fmaxf(sc[nt][2], sc[nt][3]));
        }
        mt0 = fmaxf(mt0, __shfl_xor_sync(0xFFFFFFFFu, mt0, 1));
        mt0 = fmaxf(mt0, __shfl_xor_sync(0xFFFFFFFFu, mt0, 2));
        mt1 = fmaxf(mt1, __shfl_xor_sync(0xFFFFFFFFu, mt1, 1));
        mt1 = fmaxf(mt1, __shfl_xor_sync(0xFFFFFFFFu, mt1, 2));
        float mn0 = fmaxf(m0, mt0), mn1 = fmaxf(m1, mt1);
        float corr0 = __expf(m0 - mn0), corr1 = __expf(m1 - mn1);
        float sum0 = 0.f, sum1 = 0.f;
        #pragma unroll
        for (int nt = 0; nt < 8; nt++) {
            sc[nt][0] = __expf(sc[nt][0] - mn0);
            sc[nt][1] = __expf(sc[nt][1] - mn0);
            sc[nt][2] = __expf(sc[nt][2] - mn1);
            sc[nt][3] = __expf(sc[nt][3] - mn1);
            sum0 += sc[nt][0] + sc[nt][1];
            sum1 += sc[nt][2] + sc[nt][3];
        }
        sum0 += __shfl_xor_sync(0xFFFFFFFFu, sum0, 1);
        sum0 += __shfl_xor_sync(0xFFFFFFFFu, sum0, 2);
        sum1 += __shfl_xor_sync(0xFFFFFFFFu, sum1, 1);
        sum1 += __shfl_xor_sync(0xFFFFFFFFu, sum1, 2);
        l0 = l0 * corr0 + sum0;
        l1 = l1 * corr1 + sum1;
        m0 = mn0; m1 = mn1;

        // ---- rescale O, stash P into warp-exclusive QP rows
        #pragma unroll
        for (int nt = 0; nt < 8; nt++) {
            o[nt][0] *= corr0; o[nt][1] *= corr0;
            o[nt][2] *= corr1; o[nt][3] *= corr1;
            int cc = nt * 8 + 2 * qd;
            *(float2*)&QP[rr * ATS + cc]       = make_float2(sc[nt][0], sc[nt][1]);
            *(float2*)&QP[(rr + 8) * ATS + cc] = make_float2(sc[nt][2], sc[nt][3]);
        }
        __syncwarp();

        // ---- O += P @ V
        #pragma unroll
        for (int k = 0; k < 8; k++) {
            int kb = k * 8;
            uint32_t pa[4];
            pa[0] = __float_as_uint(QP[rr * ATS + kb + qd]);
            pa[1] = __float_as_uint(QP[(rr + 8) * ATS + kb + qd]);
            pa[2] = __float_as_uint(QP[rr * ATS + kb + qd + 4]);
            pa[3] = __float_as_uint(QP[(rr + 8) * ATS + kb + qd + 4]);
            uint32_t bfr[8][2];
            #pragma unroll
            for (int nt = 0; nt < 8; nt++) {
                int nn = nt * 8 + grp;
                bfr[nt][0] = __float_as_uint(Vs[(kb + qd) * ATS + nn]);
                bfr[nt][1] = __float_as_uint(Vs[(kb + qd + 4) * ATS + nn]);
            }
            #pragma unroll
            for (int nt = 0; nt < 8; nt++)
                mma_tf32(o[nt], pa, bfr[nt]);
        }
        __syncwarp();
    }

    // ---- normalize + write out
    float inv0 = 1.0f / l0, inv1 = 1.0f / l1;
    int b = bh >> 4, hh = bh & 15;
    size_t t0 = (size_t)(b * 1024) + q0 + rr;
    #pragma unroll
    for (int nt = 0; nt < 8; nt++) {
        int cc = nt * 8 + 2 * qd;
        *(float2*)(g_o + t0 * 1024 + hh * 64 + cc) =
            make_float2(o[nt][0] * inv0, o[nt][1] * inv0);
        *(float2*)(g_o + (t0 + 8) * 1024 + hh * 64 + cc) =
            make_float2(o[nt][2] * inv1, o[nt][3] * inv1);
    }
}

// ---------------- gate softmax + pack ---------------------------------------
__global__ __launch_bounds__(256) void gate_pack_kernel()
{
    int idx = blockIdx.x * 256 + threadIdx.x;
    int mm = idx & 15;
    int hh = (idx >> 4) & 63;
    int t  = (idx >> 10) & 1023;
    int b  = idx >> 20;
    const float* g = g_gates + (size_t)idx * 17;
    float e[17];
    float mx = -1e30f;
    #pragma unroll
    for (int k = 0; k < 17; k++) { e[k] = g[k]; mx = fmaxf(mx, e[k]); }
    float sum = 0.f;
    #pragma unroll
    for (int k = 0; k < 17; k++) { e[k] = __expf(e[k] - mx); sum += e[k]; }
    float inv = 1.0f / sum;
    int bh = b * 64 + hh;
    float* Ad = g_Apack + (((size_t)bh * 1024 + t) * 16 + mm) * 16;
    #pragma unroll
    for (int k = 0; k < 16; k++) Ad[k] = e[k + 1] * inv;
    float v = g_vv[((size_t)(b * 1024 + t)) * 1024 + hh * 16 + mm];
    g_bv[((size_t)bh * 1024 + t) * 16 + mm] = e[0] * inv * v;
}

// ---------------- sequential gated scan -------------------------------------
__global__ __launch_bounds__(128) void scan_kernel()
{
    int bh = blockIdx.x;
    int b = bh >> 6, hh = bh & 63;
    __shared__ float Abuf[2][16 * 256];
    __shared__ float bvbuf[2][16 * 16];
    __shared__ float st[16];
    const float4* Ap = (const float4*)(g_Apack + (size_t)bh * 1024 * 256);
    const float4* Bp = (const float4*)(g_bv + (size_t)bh * 1024 * 16);
    int tid = threadIdx.x;
    if (tid < 16) st[tid] = 0.f;

    #pragma unroll
    for (int k = 0; k < 8; k++)
        ((float4*)Abuf[0])[tid + k * 128] = Ap[tid + k * 128];
    if (tid < 64) ((float4*)bvbuf[0])[tid] = Bp[tid];
    __syncthreads();

    int cur = 0;
    for (int c = 0; c < 64; c++) {
        float4 pf[8];
        float4 pb;
        if (c < 63) {
            #pragma unroll
            for (int k = 0; k < 8; k++)
                pf[k] = Ap[(size_t)(c + 1) * 1024 + tid + k * 128];
            if (tid < 64) pb = Bp[(size_t)(c + 1) * 64 + tid];
        }
        if (tid < 16) {
            const float4* Ab = (const float4*)Abuf[cur];
            const float* bvv = bvbuf[cur];
            float* hrow = g_hout + ((size_t)(b * 1024 + c * 16)) * 1024 + hh * 16 + tid;
            #pragma unroll 4
            for (int s = 0; s < 16; s++) {
                float4 s0 = *(const float4*)&st[0];
                float4 s1 = *(const float4*)&st[4];
                float4 s2 = *(const float4*)&st[8];
                float4 s3 = *(const float4*)&st[12];
                float4 a0 = Ab[s * 64 + tid * 4 + 0];
                float4 a1 = Ab[s * 64 + tid * 4 + 1];
                float4 a2 = Ab[s * 64 + tid * 4 + 2];
                float4 a3 = Ab[s * 64 + tid * 4 + 3];
                float p0 = fmaf(a0.x, s0.x, fmaf(a0.y, s0.y, fmaf(a0.z, s0.z, a0.w * s0.w)));
                float p1 = fmaf(a1.x, s1.x, fmaf(a1.y, s1.y, fmaf(a1.z, s1.z, a1.w * s1.w)));
                float p2 = fmaf(a2.x, s2.x, fmaf(a2.y, s2.y, fmaf(a2.z, s2.z, a2.w * s2.w)));
                float p3 = fmaf(a3.x, s3.x, fmaf(a3.y, s3.y, fmaf(a3.z, s3.z, a3.w * s3.w)));
                float acc = bvv[s * 16 + tid] + ((p0 + p1) + (p2 + p3));
                __syncwarp(0xFFFF);
                st[tid] = acc;
                __syncwarp(0xFFFF);
                hrow[(size_t)s * 1024] = acc;
            }
        }
        if (c < 63) {
            #pragma unroll
            for (int k = 0; k < 8; k++)
                ((float4*)Abuf[cur ^ 1])[tid + k * 128] = pf[k];
            if (tid < 64) ((float4*)bvbuf[cur ^ 1])[tid] = pb;
        }
        __syncthreads();
        cur ^= 1;
    }
}

// ---------------- launch ----------------------------------------------------
extern "C" void kernel_launch(void* const* d_in, const int* in_sizes, int n_in,
                              void* d_out, int out_size)
{
    const float* x    = (const float*)d_in[0];
    const float* anw  = (const float*)d_in[1];
    const float* wqkv = (const float*)d_in[2];
    const float* wao  = (const float*)d_in[3];
    const float* lnw  = (const float*)d_in[4];
    const float* wv   = (const float*)d_in[5];
    const float* wa   = (const float*)d_in[6];
    const float* wop  = (const float*)d_in[7];
    float* out = (float*)d_out;

    float *ph, *pqkv, *po, *px2, *ph2, *pvv, *pg, *phout;
    cudaGetSymbolAddress((void**)&ph,    g_h);
    cudaGetSymbolAddress((void**)&pqkv,  g_qkv);
    cudaGetSymbolAddress((void**)&po,    g_o);
    cudaGetSymbolAddress((void**)&px2,   g_x2);
    cudaGetSymbolAddress((void**)&ph2,   g_h2);
    cudaGetSymbolAddress((void**)&pvv,   g_vv);
    cudaGetSymbolAddress((void**)&pg,    g_gates);
    cudaGetSymbolAddress((void**)&phout, g_hout);

    cudaFuncSetAttribute(tc_gemm, cudaFuncAttributeMaxDynamicSharedMemorySize, GSM_TOT);
    cudaFuncSetAttribute(attn_tc_kernel, cudaFuncAttributeMaxDynamicSharedMemorySize, ATT_SMEM);

    rmsnorm_kernel<<<BT, 256>>>(x, anw, ph);
    tc_gemm<<<dim3(3072/128, BT/128), 256, GSM_TOT>>>(ph, wqkv, nullptr, pqkv, 3072, DD);
    rope_kernel<<<(2 * 1024 * 16 * 64) / 256, 256>>>();
    attn_tc_kernel<<<dim3(16, 16, 2), 128, ATT_SMEM>>>();
    tc_gemm<<<dim3(DD/128, BT/128), 256, GSM_TOT>>>(po, wao, x, px2, DD, DD);
    rmsnorm_kernel<<<BT, 256>>>(px2, lnw, ph2);
    tc_gemm<<<dim3(DD/128, BT/128), 256, GSM_TOT>>>(ph2, wv, nullptr, pvv, DD, DD);
    tc_gemm<<<dim3(NA/128, BT/128), 256, GSM_TOT>>>(ph2, wa, nullptr, pg, NA, DD);
    gate_pack_kernel<<<(2 * 1024 * 64 * 16) / 256, 256>>>();
    scan_kernel<<<128, 128>>>();
    tc_gemm<<<dim3(DD/128, BT/128), 256, GSM_TOT>>>(phout, wop, px2, out, DD, DD);
}

// round 8
// speedup vs baseline: 3.3128x; 1.0564x over previous
#include <cuda_runtime.h>
#include <math.h>
#include <stdint.h>

// B=2, T=1024, D=1024, NH=16, HD=64, H=64, M=16, N_a = H*M*(M+1) = 17408
#define BT 2048
#define DD 1024
#define NA 17408

// ---------------- scratch buffers -------------------------------------------
__device__ float g_h   [BT * DD];
__device__ float g_qkv [BT * 3 * DD];
__device__ float g_qr  [2 * 16 * 1024 * 64];
__device__ float g_kr  [2 * 16 * 1024 * 64];
__device__ float g_vb  [2 * 16 * 1024 * 64];
__device__ float g_o   [BT * DD];
__device__ float g_x2  [BT * DD];
__device__ float g_h2  [BT * DD];
__device__ float g_vv  [BT * DD];
__device__ float g_gates[(size_t)BT * NA];
__device__ float g_hout[BT * DD];

// ---------------- mma / cp.async helpers ------------------------------------
__device__ __forceinline__ void mma_tf32(float* c, const uint32_t* a, const uint32_t* b) {
    asm volatile(
        "mma.sync.aligned.m16n8k8.row.col.f32.tf32.tf32.f32 "
        "{%0,%1,%2,%3}, {%4,%5,%6,%7}, {%8,%9}, {%0,%1,%2,%3};\n"
        : "+f"(c[0]), "+f"(c[1]), "+f"(c[2]), "+f"(c[3])
        : "r"(a[0]), "r"(a[1]), "r"(a[2]), "r"(a[3]), "r"(b[0]), "r"(b[1]));
}
__device__ __forceinline__ void cp_async16(uint32_t saddr, const void* gptr) {
    asm volatile("cp.async.cg.shared.global [%0], [%1], 16;" :: "r"(saddr), "l"(gptr));
}
#define CP_COMMIT() asm volatile("cp.async.commit_group;" ::: "memory")
#define CP_WAIT2()  asm volatile("cp.async.wait_group 2;" ::: "memory")
#define CP_WAIT1()  asm volatile("cp.async.wait_group 1;" ::: "memory")
#define CP_WAIT0()  asm volatile("cp.async.wait_group 0;" ::: "memory")
__device__ __forceinline__ uint32_t smem_u32(const void* p) {
    uint32_t a;
    asm("{ .reg .u64 t; cvta.to.shared.u64 t, %1; cvt.u32.u64 %0, t; }"
        : "=r"(a) : "l"(p));
    return a;
}

// ---------------- RMSNorm ---------------------------------------------------
__global__ __launch_bounds__(256) void rmsnorm_kernel(
    const float* __restrict__ x, const float* __restrict__ w, float* __restrict__ out)
{
    int row = blockIdx.x;
    const float4* xr = (const float4*)(x + (size_t)row * DD);
    float4 xv = xr[threadIdx.x];
    float ss = xv.x*xv.x + xv.y*xv.y + xv.z*xv.z + xv.w*xv.w;
    #pragma unroll
    for (int o = 16; o > 0; o >>= 1) ss += __shfl_xor_sync(0xFFFFFFFFu, ss, o);
    __shared__ float red[8];
    if ((threadIdx.x & 31) == 0) red[threadIdx.x >> 5] = ss;
    __syncthreads();
    float tot = red[0]+red[1]+red[2]+red[3]+red[4]+red[5]+red[6]+red[7];
    float r = rsqrtf(tot * (1.0f/1024.0f) + 1e-5f);
    const float4* w4 = (const float4*)w;
    float4 wv = w4[threadIdx.x];
    float4 ov = make_float4(xv.x*r*wv.x, xv.y*r*wv.y, xv.z*r*wv.z, xv.w*r*wv.w);
    ((float4*)(out + (size_t)row * DD))[threadIdx.x] = ov;
}

// ---------------- TF32 mma.sync GEMM, BMx128x32, 3-stage, 2 CTA/SM ----------
// Warp tile 32x64; BM=128 -> 8 warps (4x2), BM=64 -> 4 warps (2x2).
#define ASTRIDE 36
#define BSTRIDE 132

template<int BM>
__global__ __launch_bounds__(BM * 2, 2) void tc_gemm(
    const float* __restrict__ A, const float* __restrict__ B,
    const float* __restrict__ Cin, float* __restrict__ C, int Nn, int Kk)
{
    constexpr int THREADS = BM * 2;
    constexpr int ABYTES_T = BM * ASTRIDE * 4;
    constexpr int STAGE_T = ABYTES_T + 32 * BSTRIDE * 4;
    extern __shared__ char smem[];
    float* sfp = (float*)smem;
    uint32_t sb = smem_u32(smem);
    int tid = threadIdx.x;
    const int brow = blockIdx.y * BM;
    const int bcol = blockIdx.x * 128;

    int w    = tid >> 5;
    int wm   = w >> 1;
    int wn   = w & 1;
    int lane = tid & 31;
    int grp  = lane >> 2;
    int qd   = lane & 3;

    float acc[2][8][4];
    #pragma unroll
    for (int i = 0; i < 2; i++)
        #pragma unroll
        for (int j = 0; j < 8; j++)
            #pragma unroll
            for (int q = 0; q < 4; q++) acc[i][j][q] = 0.f;

    const float* Ag = A + (size_t)brow * Kk;
    const int ktiles = Kk / 32;

    #define LOAD_TILE(kt, s) do {                                              \
        uint32_t ab = sb + (s) * STAGE_T;                                      \
        uint32_t bb = ab + ABYTES_T;                                           \
        _Pragma("unroll")                                                      \
        for (int it = 0; it < (BM * 8) / THREADS; it++) {                      \
            int idx = it * THREADS + tid;                                      \
            int r = idx >> 3, kq = idx & 7;                                    \
            cp_async16(ab + (uint32_t)(r * ASTRIDE + kq * 4) * 4,              \
                       Ag + (size_t)r * Kk + (kt) * 32 + kq * 4);              \
        }                                                                      \
        _Pragma("unroll")                                                      \
        for (int it = 0; it < 1024 / THREADS; it++) {                          \
            int idx = it * THREADS + tid;                                      \
            int kr = idx >> 5, n4 = (idx & 31) * 4;                            \
            cp_async16(bb + (uint32_t)(kr * BSTRIDE + n4) * 4,                 \
                       B + (size_t)((kt) * 32 + kr) * Nn + bcol + n4);         \
        }                                                                      \
        CP_COMMIT();                                                           \
    } while (0)

    LOAD_TILE(0, 0);
    if (ktiles > 1) LOAD_TILE(1, 1);

    for (int kt = 0; kt < ktiles; kt++) {
        int stg = kt - (kt / 3) * 3;
        if (kt + 2 < ktiles) {
            int s2 = (kt + 2) - ((kt + 2) / 3) * 3;
            LOAD_TILE(kt + 2, s2);
            CP_WAIT2();
        } else if (kt + 1 < ktiles) {
            CP_WAIT1();
        } else {
            CP_WAIT0();
        }
        __syncthreads();

        const float* As = sfp + (size_t)stg * (STAGE_T / 4);
        const float* Bs = As + ABYTES_T / 4;

        #pragma unroll
        for (int ks = 0; ks < 4; ks++) {
            int kb = ks * 8;
            uint32_t afr[2][4], bfr[8][2];
            #pragma unroll
            for (int i = 0; i < 2; i++) {
                int rr = wm * 32 + i * 16 + grp;
                afr[i][0] = __float_as_uint(As[rr * ASTRIDE + kb + qd]);
                afr[i][1] = __float_as_uint(As[(rr + 8) * ASTRIDE + kb + qd]);
                afr[i][2] = __float_as_uint(As[rr * ASTRIDE + kb + qd + 4]);
                afr[i][3] = __float_as_uint(As[(rr + 8) * ASTRIDE + kb + qd + 4]);
            }
            #pragma unroll
            for (int j = 0; j < 8; j++) {
                int nn = wn * 64 + j * 8 + grp;
                bfr[j][0] = __float_as_uint(Bs[(kb + qd) * BSTRIDE + nn]);
                bfr[j][1] = __float_as_uint(Bs[(kb + qd + 4) * BSTRIDE + nn]);
            }
            #pragma unroll
            for (int i = 0; i < 2; i++)
                #pragma unroll
                for (int j = 0; j < 8; j++)
                    mma_tf32(acc[i][j], afr[i], bfr[j]);
        }
        __syncthreads();
    }

    #pragma unroll
    for (int i = 0; i < 2; i++) {
        size_t row0 = (size_t)brow + wm * 32 + i * 16 + grp;
        #pragma unroll
        for (int j = 0; j < 8; j++) {
            size_t col = (size_t)bcol + wn * 64 + j * 8 + qd * 2;
            float2 v0 = make_float2(acc[i][j][0], acc[i][j][1]);
            float2 v1 = make_float2(acc[i][j][2], acc[i][j][3]);
            if (Cin) {
                float2 r0 = *(const float2*)(Cin + row0 * Nn + col);
                float2 r1 = *(const float2*)(Cin + (row0 + 8) * Nn + col);
                v0.x += r0.x; v0.y += r0.y; v1.x += r1.x; v1.y += r1.y;
            }
            *(float2*)(C + row0 * Nn + col) = v0;
            *(float2*)(C + (row0 + 8) * Nn + col) = v1;
        }
    }
    #undef LOAD_TILE
}

#define GSM128 (3 * (128 * ASTRIDE * 4 + 32 * BSTRIDE * 4))
#define GSM64  (3 * (64  * ASTRIDE * 4 + 32 * BSTRIDE * 4))

// ---------------- RoPE + repack ---------------------------------------------
__global__ __launch_bounds__(256) void rope_kernel()
{
    int idx = blockIdx.x * 256 + threadIdx.x;
    int d  = idx & 63;
    int hh = (idx >> 6) & 15;
    int t  = (idx >> 10) & 1023;
    int b  = idx >> 20;
    const float* base = g_qkv + (size_t)(b * 1024 + t) * 3072;
    float qv = base[hh * 64 + d];
    float kv = base[1024 + hh * 64 + d];
    float vv = base[2048 + hh * 64 + d];
    int i = d & 31;
    float inv = exp2f((float)i * (-13.287712379549449f / 32.0f));
    float f = (float)t * inv;
    float sn, cs;
    sincosf(f, &sn, &cs);
    float q2 = (d < 32) ? -base[hh*64 + d + 32] : base[hh*64 + d - 32];
    float k2 = (d < 32) ? -base[1024 + hh*64 + d + 32] : base[1024 + hh*64 + d - 32];
    size_t oi = ((size_t)(b * 16 + hh) * 1024 + t) * 64 + d;
    g_qr[oi] = qv * cs + q2 * sn;
    g_kr[oi] = kv * cs + k2 * sn;
    g_vb[oi] = vv;
}

// ---------------- Tensor-core flash attention --------------------------------
#define ATS 72
#define ATT_SMEM (3 * 64 * ATS * 4)

__global__ __launch_bounds__(128) void attn_tc_kernel()
{
    extern __shared__ float s[];
    float* QP = s;
    float* Ks = s + 64 * ATS;
    float* Vs = s + 2 * 64 * ATS;

    int bh = blockIdx.z * 16 + blockIdx.y;
    int q0 = blockIdx.x * 64;
    int tid = threadIdx.x;
    int w = tid >> 5, lane = tid & 31;
    int grp = lane >> 2, qd = lane & 3;
    int rr = w * 16 + grp;

    const float* Qg = g_qr + ((size_t)bh * 1024 + q0) * 64;
    #pragma unroll
    for (int it = 0; it < 8; it++) {
        int i = it * 128 + tid;
        int r = i >> 4, c = (i & 15) * 4;
        *(float4*)&QP[r * ATS + c] = *(const float4*)(Qg + (size_t)r * 64 + c);
    }
    __syncthreads();

    uint32_t qfr[8][4];
    #pragma unroll
    for (int k = 0; k < 8; k++) {
        qfr[k][0] = __float_as_uint(QP[rr * ATS + k * 8 + qd]);
        qfr[k][1] = __float_as_uint(QP[(rr + 8) * ATS + k * 8 + qd]);
        qfr[k][2] = __float_as_uint(QP[rr * ATS + k * 8 + qd + 4]);
        qfr[k][3] = __float_as_uint(QP[(rr + 8) * ATS + k * 8 + qd + 4]);
    }

    float m0 = -1e30f, m1 = -1e30f, l0 = 0.f, l1 = 0.f;
    float o[8][4];
    #pragma unroll
    for (int j = 0; j < 8; j++)
        #pragma unroll
        for (int q = 0; q < 4; q++) o[j][q] = 0.f;

    int row_g0 = q0 + rr;
    int row_g1 = row_g0 + 8;

    int ntiles = q0 / 64 + 1;
    for (int tIdx = 0; tIdx < ntiles; tIdx++) {
        int s0 = tIdx * 64;
        __syncthreads();
        const float* Kg = g_kr + ((size_t)bh * 1024 + s0) * 64;
        const float* Vg = g_vb + ((size_t)bh * 1024 + s0) * 64;
        #pragma unroll
        for (int it = 0; it < 8; it++) {
            int i = it * 128 + tid;
            int r = i >> 4, c = (i & 15) * 4;
            *(float4*)&Ks[r * ATS + c] = *(const float4*)(Kg + (size_t)r * 64 + c);
            *(float4*)&Vs[r * ATS + c] = *(const float4*)(Vg + (size_t)r * 64 + c);
        }
        __syncthreads();

        float sc[8][4];
        #pragma unroll
        for (int j = 0; j < 8; j++)
            #pragma unroll
            for (int q = 0; q < 4; q++) sc[j][q] = 0.f;
        #pragma unroll
        for (int k = 0; k < 8; k++) {
            int kb = k * 8;
            uint32_t bfr[8][2];
            #pragma unroll
            for (int nt = 0; nt < 8; nt++) {
                int nn = nt * 8 + grp;
                bfr[nt][0] = __float_as_uint(Ks[nn * ATS + kb + qd]);
                bfr[nt][1] = __float_as_uint(Ks[nn * ATS + kb + qd + 4]);
            }
            #pragma unroll
            for (int nt = 0; nt < 8; nt++)
                mma_tf32(sc[nt], qfr[k], bfr[nt]);
        }

        bool diag = (s0 == q0);
        #pragma unroll
        for (int nt = 0; nt < 8; nt++) {
            int c0 = s0 + nt * 8 + 2 * qd;
            sc[nt][0] *= 0.125f; sc[nt][1] *= 0.125f;
            sc[nt][2] *= 0.125f; sc[nt][3] *= 0.125f;
            if (diag) {
                if (c0 > row_g0)     sc[nt][0] = -1e30f;
                if (c0 + 1 > row_g0) sc[nt][1] = -1e30f;
                if (c0 > row_g1)     sc[nt][2] = -1e30f;
                if (c0 + 1 > row_g1) sc[nt][3] = -1e30f;
            }
        }

        float mt0 = -1e30f, mt1 = -1e30f;
        #pragma unroll
        for (int nt = 0; nt < 8; nt++) {
            mt0 = fmaxf(mt0, fmaxf(sc[nt][0], sc[nt][1]));
            mt1 = fmaxf(mt1, fmaxf(sc[nt][2], sc[nt][3]));
        }
        mt0 = fmaxf(mt0, __shfl_xor_sync(0xFFFFFFFFu, mt0, 1));
        mt0 = fmaxf(mt0, __shfl_xor_sync(0xFFFFFFFFu, mt0, 2));
        mt1 = fmaxf(mt1, __shfl_xor_sync(0xFFFFFFFFu, mt1, 1));
        mt1 = fmaxf(mt1, __shfl_xor_sync(0xFFFFFFFFu, mt1, 2));
        float mn0 = fmaxf(m0, mt0), mn1 = fmaxf(m1, mt1);
        float corr0 = __expf(m0 - mn0), corr1 = __expf(m1 - mn1);
        float sum0 = 0.f, sum1 = 0.f;
        #pragma unroll
        for (int nt = 0; nt < 8; nt++) {
            sc[nt][0] = __expf(sc[nt][0] - mn0);
            sc[nt][1] = __expf(sc[nt][1] - mn0);
            sc[nt][2] = __expf(sc[nt][2] - mn1);
            sc[nt][3] = __expf(sc[nt][3] - mn1);
            sum0 += sc[nt][0] + sc[nt][1];
            sum1 += sc[nt][2] + sc[nt][3];
        }
        sum0 += __shfl_xor_sync(0xFFFFFFFFu, sum0, 1);
        sum0 += __shfl_xor_sync(0xFFFFFFFFu, sum0, 2);
        sum1 += __shfl_xor_sync(0xFFFFFFFFu, sum1, 1);
        sum1 += __shfl_xor_sync(0xFFFFFFFFu, sum1, 2);
        l0 = l0 * corr0 + sum0;
        l1 = l1 * corr1 + sum1;
        m0 = mn0; m1 = mn1;

        #pragma unroll
        for (int nt = 0; nt < 8; nt++) {
            o[nt][0] *= corr0; o[nt][1] *= corr0;
            o[nt][2] *= corr1; o[nt][3] *= corr1;
            int cc = nt * 8 + 2 * qd;
            *(float2*)&QP[rr * ATS + cc]       = make_float2(sc[nt][0], sc[nt][1]);
            *(float2*)&QP[(rr + 8) * ATS + cc] = make_float2(sc[nt][2], sc[nt][3]);
        }
        __syncwarp();

        #pragma unroll
        for (int k = 0; k < 8; k++) {
            int kb = k * 8;
            uint32_t pa[4];
            pa[0] = __float_as_uint(QP[rr * ATS + kb + qd]);
            pa[1] = __float_as_uint(QP[(rr + 8) * ATS + kb + qd]);
            pa[2] = __float_as_uint(QP[rr * ATS + kb + qd + 4]);
            pa[3] = __float_as_uint(QP[(rr + 8) * ATS + kb + qd + 4]);
            uint32_t bfr[8][2];
            #pragma unroll
            for (int nt = 0; nt < 8; nt++) {
                int nn = nt * 8 + grp;
                bfr[nt][0] = __float_as_uint(Vs[(kb + qd) * ATS + nn]);
                bfr[nt][1] = __float_as_uint(Vs[(kb + qd + 4) * ATS + nn]);
            }
            #pragma unroll
            for (int nt = 0; nt < 8; nt++)
                mma_tf32(o[nt], pa, bfr[nt]);
        }
        __syncwarp();
    }

    float inv0 = 1.0f / l0, inv1 = 1.0f / l1;
    int b = bh >> 4, hh = bh & 15;
    size_t t0 = (size_t)(b * 1024) + q0 + rr;
    #pragma unroll
    for (int nt = 0; nt < 8; nt++) {
        int cc = nt * 8 + 2 * qd;
        *(float2*)(g_o + t0 * 1024 + hh * 64 + cc) =
            make_float2(o[nt][0] * inv0, o[nt][1] * inv0);
        *(float2*)(g_o + (t0 + 8) * 1024 + hh * 64 + cc) =
            make_float2(o[nt][2] * inv1, o[nt][3] * inv1);
    }
}

// ---------------- fused gate-softmax + sequential scan ----------------------
// 128 CTAs (one per b,h), 128 threads.
// Per 16-step chunk: warp 0 lanes 0-15 run recurrence, warps 2-3 softmax the
// NEXT chunk's raw gates, warp 1 cp.asyncs the chunk after that.
// Dyn smem: raw[2] (4608 f), A[2] (4096 f), bv[2] (256 f), st (16 f).
#define RAW_F 4608
#define SCAN_SMEM ((2 * RAW_F + 2 * 4096 + 2 * 256 + 16) * 4)

__global__ __launch_bounds__(128) void scan_fused_kernel()
{
    extern __shared__ float ss[];
    float* raw[2] = { ss, ss + RAW_F };
    float* Ab [2] = { ss + 2 * RAW_F, ss + 2 * RAW_F + 4096 };
    float* bv [2] = { ss + 2 * RAW_F + 8192, ss + 2 * RAW_F + 8192 + 256 };
    float* st = ss + 2 * RAW_F + 8192 + 512;
    uint32_t raw_sb[2] = { smem_u32(raw[0]), smem_u32(raw[1]) };

    int bh = blockIdx.x;
    int b = bh >> 6, hh = bh & 63;
    int tid = threadIdx.x;
    int w = tid >> 5, lane = tid & 31;

    // gmem bases for this (b, h)
    const char* gates_base = (const char*)(g_gates) + ((size_t)b * 1024) * (NA * 4) + hh * 272 * 4;
    const char* vv_base    = (const char*)(g_vv)    + ((size_t)b * 1024) * (DD * 4) + hh * 16 * 4;

    // issue all 1152 16B loads for chunk c into slot s using threads [t0, t0+nt)
    #define LOAD_RAW(c, s, t0, nt) do {                                          \
        int base_t = (c) * 16;                                                   \
        for (int j = 0; j < 1152 / (nt); j++) {                                  \
            int fid = j * (nt) + (tid - (t0));                                   \
            if (fid < 1088) {                                                    \
                int tt = fid / 68, off = fid % 68;                               \
                cp_async16(raw_sb[s] + (uint32_t)(tt * 272 + off * 4) * 4,       \
                           gates_base + (size_t)(base_t + tt) * (NA * 4) + off * 16); \
            } else {                                                             \
                int v = fid - 1088;                                              \
                int tt = v >> 2, off = v & 3;                                    \
                cp_async16(raw_sb[s] + (uint32_t)(4352 + tt * 16 + off * 4) * 4, \
                           vv_base + (size_t)(base_t + tt) * (DD * 4) + off * 16); \
            }                                                                    \
        }                                                                        \
        CP_COMMIT();                                                             \
    } while (0)

    // softmax one row r (t = r>>4, i = r&15) of slot s into A/bv slot a
    #define SOFTMAX_ROW(r, s, a) do {                                            \
        int tt = (r) >> 4, ii = (r) & 15;                                        \
        const float* g = raw[s] + tt * 272 + ii * 17;                            \
        float e[17]; float mx = -1e30f;                                          \
        _Pragma("unroll")                                                        \
        for (int k = 0; k < 17; k++) { e[k] = g[k]; mx = fmaxf(mx, e[k]); }      \
        float sum = 0.f;                                                         \
        _Pragma("unroll")                                                        \
        for (int k = 0; k < 17; k++) { e[k] = __expf(e[k] - mx); sum += e[k]; }  \
        float inv = 1.0f / sum;                                                  \
        float* Ad = Ab[a] + tt * 256 + ii * 16;                                  \
        _Pragma("unroll")                                                        \
        for (int k = 0; k < 16; k++) Ad[k] = e[k + 1] * inv;                     \
        bv[a][tt * 16 + ii] = e[0] * inv * raw[s][4352 + tt * 16 + ii];          \
    } while (0)

    // prologue: load chunks 0,1; softmax chunk 0 with all threads
    LOAD_RAW(0, 0, 0, 128);
    LOAD_RAW(1, 1, 0, 128);
    CP_WAIT0();
    __syncthreads();
    #pragma unroll
    for (int q = 0; q < 2; q++) {
        int r = q * 128 + tid;
        SOFTMAX_ROW(r, 0, 0);
    }
    if (tid < 16) st[tid] = 0.f;
    __syncthreads();

    for (int c = 0; c < 64; c++) {
        int cur = c & 1, nxt = cur ^ 1;
        if (w == 0) {
            if (lane < 16) {
                const float4* A4 = (const float4*)Ab[cur];
                const float* bvv = bv[cur];
                float* hrow = g_hout + ((size_t)(b * 1024 + c * 16)) * 1024 + hh * 16 + lane;
                #pragma unroll 4
                for (int s2 = 0; s2 < 16; s2++) {
                    float4 s0 = *(const float4*)&st[0];
                    float4 s1 = *(const float4*)&st[4];
                    float4 s2v = *(const float4*)&st[8];
                    float4 s3 = *(const float4*)&st[12];
                    float4 a0 = A4[s2 * 64 + lane * 4 + 0];
                    float4 a1 = A4[s2 * 64 + lane * 4 + 1];
                    float4 a2 = A4[s2 * 64 + lane * 4 + 2];
                    float4 a3 = A4[s2 * 64 + lane * 4 + 3];
                    float p0 = fmaf(a0.x, s0.x, fmaf(a0.y, s0.y, fmaf(a0.z, s0.z, a0.w * s0.w)));
                    float p1 = fmaf(a1.x, s1.x, fmaf(a1.y, s1.y, fmaf(a1.z, s1.z, a1.w * s1.w)));
                    float p2 = fmaf(a2.x, s2v.x, fmaf(a2.y, s2v.y, fmaf(a2.z, s2v.z, a2.w * s2v.w)));
                    float p3 = fmaf(a3.x, s3.x, fmaf(a3.y, s3.y, fmaf(a3.z, s3.z, a3.w * s3.w)));
                    float acc = bvv[s2 * 16 + lane] + ((p0 + p1) + (p2 + p3));
                    __syncwarp(0xFFFF);
                    st[lane] = acc;
                    __syncwarp(0xFFFF);
                    hrow[(size_t)s2 * 1024] = acc;
                }
            }
        } else if (w >= 2) {
            if (c < 63) {
                #pragma unroll
                for (int q = 0; q < 4; q++) {
                    int r = (w - 2) * 32 + lane + q * 64;
                    SOFTMAX_ROW(r, nxt, nxt);
                }
            }
        } else {
            if (c + 2 < 64) {
                LOAD_RAW(c + 2, cur, 32, 32);
                CP_WAIT0();
            }
        }
        __syncthreads();
    }
    #undef LOAD_RAW
    #undef SOFTMAX_ROW
}

// ---------------- launch ----------------------------------------------------
extern "C" void kernel_launch(void* const* d_in, const int* in_sizes, int n_in,
                              void* d_out, int out_size)
{
    const float* x    = (const float*)d_in[0];
    const float* anw  = (const float*)d_in[1];
    const float* wqkv = (const float*)d_in[2];
    const float* wao  = (const float*)d_in[3];
    const float* lnw  = (const float*)d_in[4];
    const float* wv   = (const float*)d_in[5];
    const float* wa   = (const float*)d_in[6];
    const float* wop  = (const float*)d_in[7];
    float* out = (float*)d_out;

    float *ph, *pqkv, *po, *px2, *ph2, *pvv, *pg, *phout;
    cudaGetSymbolAddress((void**)&ph,    g_h);
    cudaGetSymbolAddress((void**)&pqkv,  g_qkv);
    cudaGetSymbolAddress((void**)&po,    g_o);
    cudaGetSymbolAddress((void**)&px2,   g_x2);
    cudaGetSymbolAddress((void**)&ph2,   g_h2);
    cudaGetSymbolAddress((void**)&pvv,   g_vv);
    cudaGetSymbolAddress((void**)&pg,    g_gates);
    cudaGetSymbolAddress((void**)&phout, g_hout);

    cudaFuncSetAttribute(tc_gemm<128>, cudaFuncAttributeMaxDynamicSharedMemorySize, GSM128);
    cudaFuncSetAttribute(tc_gemm<64>,  cudaFuncAttributeMaxDynamicSharedMemorySize, GSM64);
    cudaFuncSetAttribute(attn_tc_kernel, cudaFuncAttributeMaxDynamicSharedMemorySize, ATT_SMEM);
    cudaFuncSetAttribute(scan_fused_kernel, cudaFuncAttributeMaxDynamicSharedMemorySize, SCAN_SMEM);

    rmsnorm_kernel<<<BT, 256>>>(x, anw, ph);
    tc_gemm<64><<<dim3(3072/128, BT/64), 128, GSM64>>>(ph, wqkv, nullptr, pqkv, 3072, DD);
    rope_kernel<<<(2 * 1024 * 16 * 64) / 256, 256>>>();
    attn_tc_kernel<<<dim3(16, 16, 2), 128, ATT_SMEM>>>();
    tc_gemm<64><<<dim3(DD/128, BT/64), 128, GSM64>>>(po, wao, x, px2, DD, DD);
    rmsnorm_kernel<<<BT, 256>>>(px2, lnw, ph2);
    tc_gemm<64><<<dim3(DD/128, BT/64), 128, GSM64>>>(ph2, wv, nullptr, pvv, DD, DD);
    tc_gemm<128><<<dim3(NA/128, BT/128), 256, GSM128>>>(ph2, wa, nullptr, pg, NA, DD);
    scan_fused_kernel<<<128, 128, SCAN_SMEM>>>();
    tc_gemm<64><<<dim3(DD/128, BT/64), 128, GSM64>>>(phout, wop, px2, out, DD, DD);
}

// round 13
// speedup vs baseline: 4.5090x; 1.3611x over previous
#include <cuda_runtime.h>
#include <cuda_bf16.h>
#include <math.h>
#include <stdint.h>

// B=2, T=1024, D=1024, NH=16, HD=64, H=64, M=16, N_a = H*M*(M+1) = 17408
#define BT 2048
#define DD 1024
#define NA 17408

// ---------------- scratch buffers -------------------------------------------
__device__ float g_h   [BT * DD];
__device__ float g_qkv [BT * 3 * DD];
__device__ float g_qr  [2 * 16 * 1024 * 64];
__device__ float g_kr  [2 * 16 * 1024 * 64];
__device__ float g_vb  [2 * 16 * 1024 * 64];
__device__ float g_o   [BT * DD];
__device__ float g_x2  [BT * DD];
__device__ float g_h2  [BT * DD];
__device__ float g_vv  [BT * DD];
__device__ float g_hout[BT * DD];
__device__ __nv_bfloat16 g_h2bf  [BT * DD];
__device__ __nv_bfloat16 g_wat_bf[(size_t)NA * DD];     // w_a transposed [N][K]
__device__ __nv_bfloat16 g_gates_bf[(size_t)BT * NA];   // bf16 gate logits

// ---------------- mma / cp.async helpers ------------------------------------
__device__ __forceinline__ void mma_tf32(float* c, const uint32_t* a, const uint32_t* b) {
    asm volatile(
        "mma.sync.aligned.m16n8k8.row.col.f32.tf32.tf32.f32 "
        "{%0,%1,%2,%3}, {%4,%5,%6,%7}, {%8,%9}, {%0,%1,%2,%3};\n"
        : "+f"(c[0]), "+f"(c[1]), "+f"(c[2]), "+f"(c[3])
        : "r"(a[0]), "r"(a[1]), "r"(a[2]), "r"(a[3]), "r"(b[0]), "r"(b[1]));
}
__device__ __forceinline__ void mma_bf16(float* c, const uint32_t* a, const uint32_t* b) {
    asm volatile(
        "mma.sync.aligned.m16n8k16.row.col.f32.bf16.bf16.f32 "
        "{%0,%1,%2,%3}, {%4,%5,%6,%7}, {%8,%9}, {%0,%1,%2,%3};\n"
        : "+f"(c[0]), "+f"(c[1]), "+f"(c[2]), "+f"(c[3])
        : "r"(a[0]), "r"(a[1]), "r"(a[2]), "r"(a[3]), "r"(b[0]), "r"(b[1]));
}
__device__ __forceinline__ void cp_async16(uint32_t saddr, const void* gptr) {
    asm volatile("cp.async.cg.shared.global [%0], [%1], 16;" :: "r"(saddr), "l"(gptr));
}
#define CP_COMMIT() asm volatile("cp.async.commit_group;" ::: "memory")
#define CP_WAIT2()  asm volatile("cp.async.wait_group 2;" ::: "memory")
#define CP_WAIT1()  asm volatile("cp.async.wait_group 1;" ::: "memory")
#define CP_WAIT0()  asm volatile("cp.async.wait_group 0;" ::: "memory")
__device__ __forceinline__ uint32_t smem_u32(const void* p) {
    uint32_t a;
    asm("{ .reg .u64 t; cvta.to.shared.u64 t, %1; cvt.u32.u64 %0, t; }"
        : "=r"(a) : "l"(p));
    return a;
}

// ---------------- RMSNorm ---------------------------------------------------
__global__ __launch_bounds__(256) void rmsnorm_kernel(
    const float* __restrict__ x, const float* __restrict__ w, float* __restrict__ out)
{
    int row = blockIdx.x;
    const float4* xr = (const float4*)(x + (size_t)row * DD);
    float4 xv = xr[threadIdx.x];
    float ss = xv.x*xv.x + xv.y*xv.y + xv.z*xv.z + xv.w*xv.w;
    #pragma unroll
    for (int o = 16; o > 0; o >>= 1) ss += __shfl_xor_sync(0xFFFFFFFFu, ss, o);
    __shared__ float red[8];
    if ((threadIdx.x & 31) == 0) red[threadIdx.x >> 5] = ss;
    __syncthreads();
    float tot = red[0]+red[1]+red[2]+red[3]+red[4]+red[5]+red[6]+red[7];
    float r = rsqrtf(tot * (1.0f/1024.0f) + 1e-5f);
    const float4* w4 = (const float4*)w;
    float4 wv = w4[threadIdx.x];
    float4 ov = make_float4(xv.x*r*wv.x, xv.y*r*wv.y, xv.z*r*wv.z, xv.w*r*wv.w);
    ((float4*)(out + (size_t)row * DD))[threadIdx.x] = ov;
}

// ---------------- TF32 mma.sync GEMM, BMx128x32, 3-stage, 2 CTA/SM ----------
#define ASTRIDE 36
#define BSTRIDE 132

template<int BM>
__global__ __launch_bounds__(BM * 2, 2) void tc_gemm(
    const float* __restrict__ A, const float* __restrict__ B,
    const float* __restrict__ Cin, float* __restrict__ C, int Nn, int Kk)
{
    constexpr int THREADS = BM * 2;
    constexpr int ABYTES_T = BM * ASTRIDE * 4;
    constexpr int STAGE_T = ABYTES_T + 32 * BSTRIDE * 4;
    extern __shared__ char smem[];
    float* sfp = (float*)smem;
    uint32_t sb = smem_u32(smem);
    int tid = threadIdx.x;
    const int brow = blockIdx.y * BM;
    const int bcol = blockIdx.x * 128;

    int w    = tid >> 5;
    int wm   = w >> 1;
    int wn   = w & 1;
    int lane = tid & 31;
    int grp  = lane >> 2;
    int qd   = lane & 3;

    float acc[2][8][4];
    #pragma unroll
    for (int i = 0; i < 2; i++)
        #pragma unroll
        for (int j = 0; j < 8; j++)
            #pragma unroll
            for (int q = 0; q < 4; q++) acc[i][j][q] = 0.f;

    const float* Ag = A + (size_t)brow * Kk;
    const int ktiles = Kk / 32;

    #define LOAD_TILE(kt, s) do {                                              \
        uint32_t ab = sb + (s) * STAGE_T;                                      \
        uint32_t bb = ab + ABYTES_T;                                           \
        _Pragma("unroll")                                                      \
        for (int it = 0; it < (BM * 8) / THREADS; it++) {                      \
            int idx = it * THREADS + tid;                                      \
            int r = idx >> 3, kq = idx & 7;                                    \
            cp_async16(ab + (uint32_t)(r * ASTRIDE + kq * 4) * 4,              \
                       Ag + (size_t)r * Kk + (kt) * 32 + kq * 4);              \
        }                                                                      \
        _Pragma("unroll")                                                      \
        for (int it = 0; it < 1024 / THREADS; it++) {                          \
            int idx = it * THREADS + tid;                                      \
            int kr = idx >> 5, n4 = (idx & 31) * 4;                            \
            cp_async16(bb + (uint32_t)(kr * BSTRIDE + n4) * 4,                 \
                       B + (size_t)((kt) * 32 + kr) * Nn + bcol + n4);         \
        }                                                                      \
        CP_COMMIT();                                                           \
    } while (0)

    LOAD_TILE(0, 0);
    if (ktiles > 1) LOAD_TILE(1, 1);

    for (int kt = 0; kt < ktiles; kt++) {
        int stg = kt - (kt / 3) * 3;
        if (kt + 2 < ktiles) {
            int s2 = (kt + 2) - ((kt + 2) / 3) * 3;
            LOAD_TILE(kt + 2, s2);
            CP_WAIT2();
        } else if (kt + 1 < ktiles) {
            CP_WAIT1();
        } else {
            CP_WAIT0();
        }
        __syncthreads();

        const float* As = sfp + (size_t)stg * (STAGE_T / 4);
        const float* Bs = As + ABYTES_T / 4;

        #pragma unroll
        for (int ks = 0; ks < 4; ks++) {
            int kb = ks * 8;
            uint32_t afr[2][4], bfr[8][2];
            #pragma unroll
            for (int i = 0; i < 2; i++) {
                int rr = wm * 32 + i * 16 + grp;
                afr[i][0] = __float_as_uint(As[rr * ASTRIDE + kb + qd]);
                afr[i][1] = __float_as_uint(As[(rr + 8) * ASTRIDE + kb + qd]);
                afr[i][2] = __float_as_uint(As[rr * ASTRIDE + kb + qd + 4]);
                afr[i][3] = __float_as_uint(As[(rr + 8) * ASTRIDE + kb + qd + 4]);
            }
            #pragma unroll
            for (int j = 0; j < 8; j++) {
                int nn = wn * 64 + j * 8 + grp;
                bfr[j][0] = __float_as_uint(Bs[(kb + qd) * BSTRIDE + nn]);
                bfr[j][1] = __float_as_uint(Bs[(kb + qd + 4) * BSTRIDE + nn]);
            }
            #pragma unroll
            for (int i = 0; i < 2; i++)
                #pragma unroll
                for (int j = 0; j < 8; j++)
                    mma_tf32(acc[i][j], afr[i], bfr[j]);
        }
        __syncthreads();
    }

    #pragma unroll
    for (int i = 0; i < 2; i++) {
        size_t row0 = (size_t)brow + wm * 32 + i * 16 + grp;
        #pragma unroll
        for (int j = 0; j < 8; j++) {
            size_t col = (size_t)bcol + wn * 64 + j * 8 + qd * 2;
            float2 v0 = make_float2(acc[i][j][0], acc[i][j][1]);
            float2 v1 = make_float2(acc[i][j][2], acc[i][j][3]);
            if (Cin) {
                float2 r0 = *(const float2*)(Cin + row0 * Nn + col);
                float2 r1 = *(const float2*)(Cin + (row0 + 8) * Nn + col);
                v0.x += r0.x; v0.y += r0.y; v1.x += r1.x; v1.y += r1.y;
            }
            *(float2*)(C + row0 * Nn + col) = v0;
            *(float2*)(C + (row0 + 8) * Nn + col) = v1;
        }
    }
    #undef LOAD_TILE
}

#define GSM128 (3 * (128 * ASTRIDE * 4 + 32 * BSTRIDE * 4))
#define GSM64  (3 * (64  * ASTRIDE * 4 + 32 * BSTRIDE * 4))

// ---------------- BF16 GEMM for gates: 128x128x32, swizzled 64B rows --------
#define BF_AB 8192
#define BF_STAGE (2 * BF_AB)
#define GSMBF (3 * BF_STAGE)

__device__ __forceinline__ uint32_t bfswz(int r, int wcol) {
    return (uint32_t)(r * 64 + (((wcol >> 2) ^ ((r >> 1) & 3)) * 16) + (wcol & 3) * 4);
}

__global__ __launch_bounds__(256, 2) void bf_gemm(
    const __nv_bfloat16* __restrict__ A, const __nv_bfloat16* __restrict__ Bt,
    __nv_bfloat16* __restrict__ C, int Nn, int Kk)
{
    extern __shared__ char smem[];
    uint32_t sb = smem_u32(smem);
    int tid = threadIdx.x;
    const int brow = blockIdx.y * 128;
    const int bcol = blockIdx.x * 128;

    int w    = tid >> 5;
    int wm   = w >> 1;
    int wn   = w & 1;
    int lane = tid & 31;
    int grp  = lane >> 2;
    int qd   = lane & 3;

    float acc[2][8][4];
    #pragma unroll
    for (int i = 0; i < 2; i++)
        #pragma unroll
        for (int j = 0; j < 8; j++)
            #pragma unroll
            for (int q = 0; q < 4; q++) acc[i][j][q] = 0.f;

    const __nv_bfloat16* Ag = A  + (size_t)brow * Kk;
    const __nv_bfloat16* Bg = Bt + (size_t)bcol * Kk;
    const int ktiles = Kk / 32;

    #define LOAD_TILE_BF(kt, s) do {                                           \
        uint32_t ab = sb + (s) * BF_STAGE;                                     \
        uint32_t bb = ab + BF_AB;                                              \
        _Pragma("unroll")                                                      \
        for (int it = 0; it < 2; it++) {                                       \
            int idx = it * 256 + tid;                                          \
            int r = idx >> 2, kq = idx & 3;                                    \
            uint32_t so = (uint32_t)(r * 64 + ((kq ^ ((r >> 1) & 3)) * 16));   \
            cp_async16(ab + so, Ag + (size_t)r * Kk + (kt) * 32 + kq * 8);     \
            cp_async16(bb + so, Bg + (size_t)r * Kk + (kt) * 32 + kq * 8);     \
        }                                                                      \
        CP_COMMIT();                                                           \
    } while (0)

    LOAD_TILE_BF(0, 0);
    LOAD_TILE_BF(1, 1);

    for (int kt = 0; kt < ktiles; kt++) {
        int stg = kt - (kt / 3) * 3;
        if (kt + 2 < ktiles) {
            int s2 = (kt + 2) - ((kt + 2) / 3) * 3;
            LOAD_TILE_BF(kt + 2, s2);
            CP_WAIT2();
        } else if (kt + 1 < ktiles) {
            CP_WAIT1();
        } else {
            CP_WAIT0();
        }
        __syncthreads();

        const char* As = smem + stg * BF_STAGE;
        const char* Bs = As + BF_AB;

        #pragma unroll
        for (int s = 0; s < 2; s++) {           // two k16 steps
            uint32_t afr[2][4], bfr[8][2];
            int wc = s * 8 + qd;
            #pragma unroll
            for (int i = 0; i < 2; i++) {
                int r0 = wm * 32 + i * 16 + grp;
                afr[i][0] = *(const uint32_t*)(As + bfswz(r0,     wc));
                afr[i][1] = *(const uint32_t*)(As + bfswz(r0 + 8, wc));
                afr[i][2] = *(const uint32_t*)(As + bfswz(r0,     wc + 4));
                afr[i][3] = *(const uint32_t*)(As + bfswz(r0 + 8, wc + 4));
            }
            #pragma unroll
            for (int nt = 0; nt < 8; nt++) {
                int nn = wn * 64 + nt * 8 + grp;
                bfr[nt][0] = *(const uint32_t*)(Bs + bfswz(nn, wc));
                bfr[nt][1] = *(const uint32_t*)(Bs + bfswz(nn, wc + 4));
            }
            #pragma unroll
            for (int i = 0; i < 2; i++)
                #pragma unroll
                for (int nt = 0; nt < 8; nt++)
                    mma_bf16(acc[i][nt], afr[i], bfr[nt]);
        }
        __syncthreads();
    }

    #pragma unroll
    for (int i = 0; i < 2; i++) {
        size_t row0 = (size_t)brow + wm * 32 + i * 16 + grp;
        #pragma unroll
        for (int j = 0; j < 8; j++) {
            size_t col = (size_t)bcol + wn * 64 + j * 8 + qd * 2;
            __nv_bfloat162 p0 = __floats2bfloat162_rn(acc[i][j][0], acc[i][j][1]);
            __nv_bfloat162 p1 = __floats2bfloat162_rn(acc[i][j][2], acc[i][j][3]);
            *(__nv_bfloat162*)(C + row0 * Nn + col) = p0;
            *(__nv_bfloat162*)(C + (row0 + 8) * Nn + col) = p1;
        }
    }
    #undef LOAD_TILE_BF
}

// ---------------- converters -------------------------------------------------
__global__ __launch_bounds__(256) void h2bf_kernel()
{
    int i = blockIdx.x * 256 + threadIdx.x;          // x4 floats
    float4 v = ((const float4*)g_h2)[i];
    __nv_bfloat162 lo = __floats2bfloat162_rn(v.x, v.y);
    __nv_bfloat162 hi = __floats2bfloat162_rn(v.z, v.w);
    uint2 pk;
    pk.x = *(uint32_t*)&lo;
    pk.y = *(uint32_t*)&hi;
    ((uint2*)g_h2bf)[i] = pk;
}

__global__ __launch_bounds__(256) void wa_transpose_bf_kernel(const float* __restrict__ in)
{
    __shared__ float t[32][33];
    int bx = blockIdx.x * 32;   // N dim
    int by = blockIdx.y * 32;   // K dim
    int x = threadIdx.x & 31;
    int y0 = threadIdx.x >> 5;
    #pragma unroll
    for (int y = y0; y < 32; y += 8)
        t[y][x] = in[(size_t)(by + y) * NA + bx + x];
    __syncthreads();
    #pragma unroll
    for (int y = y0; y < 32; y += 8)
        g_wat_bf[(size_t)(bx + y) * 1024 + by + x] = __float2bfloat16(t[x][y]);
}

// ---------------- RoPE + repack ---------------------------------------------
__global__ __launch_bounds__(256) void rope_kernel()
{
    int idx = blockIdx.x * 256 + threadIdx.x;
    int d  = idx & 63;
    int hh = (idx >> 6) & 15;
    int t  = (idx >> 10) & 1023;
    int b  = idx >> 20;
    const float* base = g_qkv + (size_t)(b * 1024 + t) * 3072;
    float qv = base[hh * 64 + d];
    float kv = base[1024 + hh * 64 + d];
    float vv = base[2048 + hh * 64 + d];
    int i = d & 31;
    float inv = exp2f((float)i * (-13.287712379549449f / 32.0f));
    float f = (float)t * inv;
    float sn, cs;
    sincosf(f, &sn, &cs);
    float q2 = (d < 32) ? -base[hh*64 + d + 32] : base[hh*64 + d - 32];
    float k2 = (d < 32) ? -base[1024 + hh*64 + d + 32] : base[1024 + hh*64 + d - 32];
    size_t oi = ((size_t)(b * 16 + hh) * 1024 + t) * 64 + d;
    g_qr[oi] = qv * cs + q2 * sn;
    g_kr[oi] = kv * cs + k2 * sn;
    g_vb[oi] = vv;
}

// ---------------- Tensor-core flash attention --------------------------------
#define ATS 72
#define ATT_SMEM (3 * 64 * ATS * 4)

__global__ __launch_bounds__(128) void attn_tc_kernel()
{
    extern __shared__ float s[];
    float* QP = s;
    float* Ks = s + 64 * ATS;
    float* Vs = s + 2 * 64 * ATS;

    int bh = blockIdx.z * 16 + blockIdx.y;
    int q0 = blockIdx.x * 64;
    int tid = threadIdx.x;
    int w = tid >> 5, lane = tid & 31;
    int grp = lane >> 2, qd = lane & 3;
    int rr = w * 16 + grp;

    const float* Qg = g_qr + ((size_t)bh * 1024 + q0) * 64;
    #pragma unroll
    for (int it = 0; it < 8; it++) {
        int i = it * 128 + tid;
        int r = i >> 4, c = (i & 15) * 4;
        *(float4*)&QP[r * ATS + c] = *(const float4*)(Qg + (size_t)r * 64 + c);
    }
    __syncthreads();

    uint32_t qfr[8][4];
    #pragma unroll
    for (int k = 0; k < 8; k++) {
        qfr[k][0] = __float_as_uint(QP[rr * ATS + k * 8 + qd]);
        qfr[k][1] = __float_as_uint(QP[(rr + 8) * ATS + k * 8 + qd]);
        qfr[k][2] = __float_as_uint(QP[rr * ATS + k * 8 + qd + 4]);
        qfr[k][3] = __float_as_uint(QP[(rr + 8) * ATS + k * 8 + qd + 4]);
    }

    float m0 = -1e30f, m1 = -1e30f, l0 = 0.f, l1 = 0.f;
    float o[8][4];
    #pragma unroll
    for (int j = 0; j < 8; j++)
        #pragma unroll
        for (int q = 0; q < 4; q++) o[j][q] = 0.f;

    int row_g0 = q0 + rr;
    int row_g1 = row_g0 + 8;

    int ntiles = q0 / 64 + 1;
    for (int tIdx = 0; tIdx < ntiles; tIdx++) {
        int s0 = tIdx * 64;
        __syncthreads();
        const float* Kg = g_kr + ((size_t)bh * 1024 + s0) * 64;
        const float* Vg = g_vb + ((size_t)bh * 1024 + s0) * 64;
        #pragma unroll
        for (int it = 0; it < 8; it++) {
            int i = it * 128 + tid;
            int r = i >> 4, c = (i & 15) * 4;
            *(float4*)&Ks[r * ATS + c] = *(const float4*)(Kg + (size_t)r * 64 + c);
            *(float4*)&Vs[r * ATS + c] = *(const float4*)(Vg + (size_t)r * 64 + c);
        }
        __syncthreads();

        float sc[8][4];
        #pragma unroll
        for (int j = 0; j < 8; j++)
            #pragma unroll
            for (int q = 0; q < 4; q++) sc[j][q] = 0.f;
        #pragma unroll
        for (int k = 0; k < 8; k++) {
            int kb = k * 8;
            uint32_t bfr[8][2];
            #pragma unroll
            for (int nt = 0; nt < 8; nt++) {
                int nn = nt * 8 + grp;
                bfr[nt][0] = __float_as_uint(Ks[nn * ATS + kb + qd]);
                bfr[nt][1] = __float_as_uint(Ks[nn * ATS + kb + qd + 4]);
            }
            #pragma unroll
            for (int nt = 0; nt < 8; nt++)
                mma_tf32(sc[nt], qfr[k], bfr[nt]);
        }

        bool diag = (s0 == q0);
        #pragma unroll
        for (int nt = 0; nt < 8; nt++) {
            int c0 = s0 + nt * 8 + 2 * qd;
            sc[nt][0] *= 0.125f; sc[nt][1] *= 0.125f;
            sc[nt][2] *= 0.125f; sc[nt][3] *= 0.125f;
            if (diag) {
                if (c0 > row_g0)     sc[nt][0] = -1e30f;
                if (c0 + 1 > row_g0) sc[nt][1] = -1e30f;
                if (c0 > row_g1)     sc[nt][2] = -1e30f;
                if (c0 + 1 > row_g1) sc[nt][3] = -1e30f;
            }
        }

        float mt0 = -1e30f, mt1 = -1e30f;
        #pragma unroll
        for (int nt = 0; nt < 8; nt++) {
            mt0 = fmaxf(mt0, fmaxf(sc[nt][0], sc[nt][1]));
            mt1 = fmaxf(mt1, fmaxf(sc[nt][2], sc[nt][3]));
        }
        mt0 = fmaxf(mt0, __shfl_xor_sync(0xFFFFFFFFu, mt0, 1));
        mt0 = fmaxf(mt0, __shfl_xor_sync(0xFFFFFFFFu, mt0, 2));
        mt1 = fmaxf(mt1, __shfl_xor_sync(0xFFFFFFFFu, mt1, 1));
        mt1 = fmaxf(mt1, __shfl_xor_sync(0xFFFFFFFFu, mt1, 2));
        float mn0 = fmaxf(m0, mt0), mn1 = fmaxf(m1, mt1);
        float corr0 = __expf(m0 - mn0), corr1 = __expf(m1 - mn1);
        float sum0 = 0.f, sum1 = 0.f;
        #pragma unroll
        for (int nt = 0; nt < 8; nt++) {
            sc[nt][0] = __expf(sc[nt][0] - mn0);
            sc[nt][1] = __expf(sc[nt][1] - mn0);
            sc[nt][2] = __expf(sc[nt][2] - mn1);
            sc[nt][3] = __expf(sc[nt][3] - mn1);
            sum0 += sc[nt][0] + sc[nt][1];
            sum1 += sc[nt][2] + sc[nt][3];
        }
        sum0 += __shfl_xor_sync(0xFFFFFFFFu, sum0, 1);
        sum0 += __shfl_xor_sync(0xFFFFFFFFu, sum0, 2);
        sum1 += __shfl_xor_sync(0xFFFFFFFFu, sum1, 1);
        sum1 += __shfl_xor_sync(0xFFFFFFFFu, sum1, 2);
        l0 = l0 * corr0 + sum0;
        l1 = l1 * corr1 + sum1;
        m0 = mn0; m1 = mn1;

        #pragma unroll
        for (int nt = 0; nt < 8; nt++) {
            o[nt][0] *= corr0; o[nt][1] *= corr0;
            o[nt][2] *= corr1; o[nt][3] *= corr1;
            int cc = nt * 8 + 2 * qd;
            *(float2*)&QP[rr * ATS + cc]       = make_float2(sc[nt][0], sc[nt][1]);
            *(float2*)&QP[(rr + 8) * ATS + cc] = make_float2(sc[nt][2], sc[nt][3]);
        }
        __syncwarp();

        #pragma unroll
        for (int k = 0; k < 8; k++) {
            int kb = k * 8;
            uint32_t pa[4];
            pa[0] = __float_as_uint(QP[rr * ATS + kb + qd]);
            pa[1] = __float_as_uint(QP[(rr + 8) * ATS + kb + qd]);
            pa[2] = __float_as_uint(QP[rr * ATS + kb + qd + 4]);
            pa[3] = __float_as_uint(QP[(rr + 8) * ATS + kb + qd + 4]);
            uint32_t bfr[8][2];
            #pragma unroll
            for (int nt = 0; nt < 8; nt++) {
                int nn = nt * 8 + grp;
                bfr[nt][0] = __float_as_uint(Vs[(kb + qd) * ATS + nn]);
                bfr[nt][1] = __float_as_uint(Vs[(kb + qd + 4) * ATS + nn]);
            }
            #pragma unroll
            for (int nt = 0; nt < 8; nt++)
                mma_tf32(o[nt], pa, bfr[nt]);
        }
        __syncwarp();
    }

    float inv0 = 1.0f / l0, inv1 = 1.0f / l1;
    int b = bh >> 4, hh = bh & 15;
    size_t t0 = (size_t)(b * 1024) + q0 + rr;
    #pragma unroll
    for (int nt = 0; nt < 8; nt++) {
        int cc = nt * 8 + 2 * qd;
        *(float2*)(g_o + t0 * 1024 + hh * 64 + cc) =
            make_float2(o[nt][0] * inv0, o[nt][1] * inv0);
        *(float2*)(g_o + (t0 + 8) * 1024 + hh * 64 + cc) =
            make_float2(o[nt][2] * inv1, o[nt][3] * inv1);
    }
}

// ---------------- fused gate-softmax + sequential scan (bf16 gates) ---------
#define RAW_F 2432
#define SCAN_SMEM ((2 * RAW_F + 2 * 4096 + 2 * 256 + 16) * 4)

__global__ __launch_bounds__(128) void scan_fused_kernel()
{
    extern __shared__ float ss[];
    float* raw[2] = { ss, ss + RAW_F };
    float* Ab [2] = { ss + 2 * RAW_F, ss + 2 * RAW_F + 4096 };
    float* bv [2] = { ss + 2 * RAW_F + 8192, ss + 2 * RAW_F + 8192 + 256 };
    float* st = ss + 2 * RAW_F + 8192 + 512;
    uint32_t raw_sb[2] = { smem_u32(raw[0]), smem_u32(raw[1]) };

    int bh = blockIdx.x;
    int b = bh >> 6, hh = bh & 63;
    int tid = threadIdx.x;
    int w = tid >> 5, lane = tid & 31;

    const char* gates_base = (const char*)(g_gates_bf) + ((size_t)b * 1024) * (NA * 2) + hh * 272 * 2;
    const char* vv_base    = (const char*)(g_vv)       + ((size_t)b * 1024) * (DD * 4) + hh * 16 * 4;

    #define LOAD_RAW(c, s, t0, nt) do {                                          \
        int base_t = (c) * 16;                                                   \
        for (int j = 0; j * (nt) < 608; j++) {                                   \
            int fid = j * (nt) + (tid - (t0));                                   \
            if (fid < 544) {                                                     \
                int tt = fid / 34, off = fid % 34;                               \
                cp_async16(raw_sb[s] + (uint32_t)(tt * 544 + off * 16),          \
                           gates_base + (size_t)(base_t + tt) * (NA * 2) + off * 16); \
            } else if (fid < 608) {                                              \
                int v = fid - 544;                                               \
                int tt = v >> 2, off = v & 3;                                    \
                cp_async16(raw_sb[s] + (uint32_t)(8704 + tt * 64 + off * 16),    \
                           vv_base + (size_t)(base_t + tt) * (DD * 4) + off * 16); \
            }                                                                    \
        }                                                                        \
        CP_COMMIT();                                                             \
    } while (0)

    #define SOFTMAX_ROW(r, s, a) do {                                            \
        int tt = (r) >> 4, ii = (r) & 15;                                        \
        const __nv_bfloat16* g = (const __nv_bfloat16*)raw[s] + tt * 272 + ii * 17; \
        float e[17]; float mx = -1e30f;                                          \
        _Pragma("unroll")                                                        \
        for (int k = 0; k < 17; k++) { e[k] = __bfloat162float(g[k]); mx = fmaxf(mx, e[k]); } \
        float sum = 0.f;                                                         \
        _Pragma("unroll")                                                        \
        for (int k = 0; k < 17; k++) { e[k] = __expf(e[k] - mx); sum += e[k]; }  \
        float inv = 1.0f / sum;                                                  \
        float* Ad = Ab[a] + tt * 256 + ii * 16;                                  \
        _Pragma("unroll")                                                        \
        for (int k = 0; k < 16; k++) Ad[k] = e[k + 1] * inv;                     \
        bv[a][tt * 16 + ii] = e[0] * inv * raw[s][2176 + tt * 16 + ii];          \
    } while (0)

    LOAD_RAW(0, 0, 0, 128);
    LOAD_RAW(1, 1, 0, 128);
    CP_WAIT0();
    __syncthreads();
    #pragma unroll
    for (int q = 0; q < 2; q++) {
        int r = q * 128 + tid;
        SOFTMAX_ROW(r, 0, 0);
    }
    if (tid < 16) st[tid] = 0.f;
    __syncthreads();

    for (int c = 0; c < 64; c++) {
        int cur = c & 1, nxt = cur ^ 1;
        if (w == 0) {
            if (lane < 16) {
                const float4* A4 = (const float4*)Ab[cur];
                const float* bvv = bv[cur];
                float* hrow = g_hout + ((size_t)(b * 1024 + c * 16)) * 1024 + hh * 16 + lane;
                #pragma unroll 4
                for (int s2 = 0; s2 < 16; s2++) {
                    float4 s0 = *(const float4*)&st[0];
                    float4 s1 = *(const float4*)&st[4];
                    float4 s2v = *(const float4*)&st[8];
                    float4 s3 = *(const float4*)&st[12];
                    float4 a0 = A4[s2 * 64 + lane * 4 + 0];
                    float4 a1 = A4[s2 * 64 + lane * 4 + 1];
                    float4 a2 = A4[s2 * 64 + lane * 4 + 2];
                    float4 a3 = A4[s2 * 64 + lane * 4 + 3];
                    float p0 = fmaf(a0.x, s0.x, fmaf(a0.y, s0.y, fmaf(a0.z, s0.z, a0.w * s0.w)));
                    float p1 = fmaf(a1.x, s1.x, fmaf(a1.y, s1.y, fmaf(a1.z, s1.z, a1.w * s1.w)));
                    float p2 = fmaf(a2.x, s2v.x, fmaf(a2.y, s2v.y, fmaf(a2.z, s2v.z, a2.w * s2v.w)));
                    float p3 = fmaf(a3.x, s3.x, fmaf(a3.y, s3.y, fmaf(a3.z, s3.z, a3.w * s3.w)));
                    float acc = bvv[s2 * 16 + lane] + ((p0 + p1) + (p2 + p3));
                    __syncwarp(0xFFFF);
                    st[lane] = acc;
                    __syncwarp(0xFFFF);
                    hrow[(size_t)s2 * 1024] = acc;
                }
            }
        } else if (w >= 2) {
            if (c < 63) {
                #pragma unroll
                for (int q = 0; q < 4; q++) {
                    int r = (w - 2) * 32 + lane + q * 64;
                    SOFTMAX_ROW(r, nxt, nxt);
                }
            }
        } else {
            if (c + 2 < 64) {
                LOAD_RAW(c + 2, cur, 32, 32);
                CP_WAIT0();
            }
        }
        __syncthreads();
    }
    #undef LOAD_RAW
    #undef SOFTMAX_ROW
}

// ---------------- launch ----------------------------------------------------
extern "C" void kernel_launch(void* const* d_in, const int* in_sizes, int n_in,
                              void* d_out, int out_size)
{
    const float* x    = (const float*)d_in[0];
    const float* anw  = (const float*)d_in[1];
    const float* wqkv = (const float*)d_in[2];
    const float* wao  = (const float*)d_in[3];
    const float* lnw  = (const float*)d_in[4];
    const float* wv   = (const float*)d_in[5];
    const float* wa   = (const float*)d_in[6];
    const float* wop  = (const float*)d_in[7];
    float* out = (float*)d_out;

    float *ph, *pqkv, *po, *px2, *ph2, *pvv, *phout;
    __nv_bfloat16 *ph2bf, *pwat, *pgbf;
    cudaGetSymbolAddress((void**)&ph,    g_h);
    cudaGetSymbolAddress((void**)&pqkv,  g_qkv);
    cudaGetSymbolAddress((void**)&po,    g_o);
    cudaGetSymbolAddress((void**)&px2,   g_x2);
    cudaGetSymbolAddress((void**)&ph2,   g_h2);
    cudaGetSymbolAddress((void**)&pvv,   g_vv);
    cudaGetSymbolAddress((void**)&phout, g_hout);
    cudaGetSymbolAddress((void**)&ph2bf, g_h2bf);
    cudaGetSymbolAddress((void**)&pwat,  g_wat_bf);
    cudaGetSymbolAddress((void**)&pgbf,  g_gates_bf);

    cudaFuncSetAttribute(tc_gemm<128>, cudaFuncAttributeMaxDynamicSharedMemorySize, GSM128);
    cudaFuncSetAttribute(tc_gemm<64>,  cudaFuncAttributeMaxDynamicSharedMemorySize, GSM64);
    cudaFuncSetAttribute(bf_gemm, cudaFuncAttributeMaxDynamicSharedMemorySize, GSMBF);
    cudaFuncSetAttribute(attn_tc_kernel, cudaFuncAttributeMaxDynamicSharedMemorySize, ATT_SMEM);
    cudaFuncSetAttribute(scan_fused_kernel, cudaFuncAttributeMaxDynamicSharedMemorySize, SCAN_SMEM);

    wa_transpose_bf_kernel<<<dim3(NA/32, 32), 256>>>(wa);

    rmsnorm_kernel<<<BT, 256>>>(x, anw, ph);
    tc_gemm<64><<<dim3(3072/128, BT/64), 128, GSM64>>>(ph, wqkv, nullptr, pqkv, 3072, DD);
    rope_kernel<<<(2 * 1024 * 16 * 64) / 256, 256>>>();
    attn_tc_kernel<<<dim3(16, 16, 2), 128, ATT_SMEM>>>();
    tc_gemm<64><<<dim3(DD/128, BT/64), 128, GSM64>>>(po, wao, x, px2, DD, DD);
    rmsnorm_kernel<<<BT, 256>>>(px2, lnw, ph2);
    h2bf_kernel<<<(BT * DD / 4) / 256, 256>>>();
    tc_gemm<64><<<dim3(DD/128, BT/64), 128, GSM64>>>(ph2, wv, nullptr, pvv, DD, DD);
    bf_gemm<<<dim3(NA/128, BT/128), 256, GSMBF>>>(ph2bf, pwat, pgbf, NA, DD);
    scan_fused_kernel<<<128, 128, SCAN_SMEM>>>();
    tc_gemm<64><<<dim3(DD/128, BT/64), 128, GSM64>>>(phout, wop, px2, out, DD, DD);
}

// round 16
// speedup vs baseline: 5.3820x; 1.1936x over previous
#include <cuda_runtime.h>
#include <cuda_bf16.h>
#include <math.h>
#include <stdint.h>

// B=2, T=1024, D=1024, NH=16, HD=64, H=64, M=16, N_a = H*M*(M+1) = 17408
#define BT 2048
#define DD 1024
#define NA 17408

// ---------------- scratch buffers -------------------------------------------
__device__ __nv_bfloat16 g_hbf  [BT * DD];
__device__ float g_qkv [BT * 3 * DD];
__device__ float g_qr  [2 * 16 * 1024 * 64];
__device__ float g_kr  [2 * 16 * 1024 * 64];
__device__ float g_vb  [2 * 16 * 1024 * 64];
__device__ __nv_bfloat16 g_obf [BT * DD];
__device__ float g_x2  [BT * DD];
__device__ __nv_bfloat16 g_h2bf[BT * DD];
__device__ float g_vv  [BT * DD];
__device__ __nv_bfloat16 g_houtbf[BT * DD];
__device__ __nv_bfloat16 g_gates_bf[(size_t)BT * NA];
// transposed bf16 weights [N][K]
__device__ __nv_bfloat16 g_wqkv_t[3 * DD * DD];
__device__ __nv_bfloat16 g_wao_t [DD * DD];
__device__ __nv_bfloat16 g_wv_t  [DD * DD];
__device__ __nv_bfloat16 g_wop_t [DD * DD];
__device__ __nv_bfloat16 g_wat_bf[(size_t)NA * DD];

// ---------------- mma / cp.async helpers ------------------------------------
__device__ __forceinline__ void mma_tf32(float* c, const uint32_t* a, const uint32_t* b) {
    asm volatile(
        "mma.sync.aligned.m16n8k8.row.col.f32.tf32.tf32.f32 "
        "{%0,%1,%2,%3}, {%4,%5,%6,%7}, {%8,%9}, {%0,%1,%2,%3};\n"
        : "+f"(c[0]), "+f"(c[1]), "+f"(c[2]), "+f"(c[3])
        : "r"(a[0]), "r"(a[1]), "r"(a[2]), "r"(a[3]), "r"(b[0]), "r"(b[1]));
}
__device__ __forceinline__ void mma_bf16(float* c, const uint32_t* a, const uint32_t* b) {
    asm volatile(
        "mma.sync.aligned.m16n8k16.row.col.f32.bf16.bf16.f32 "
        "{%0,%1,%2,%3}, {%4,%5,%6,%7}, {%8,%9}, {%0,%1,%2,%3};\n"
        : "+f"(c[0]), "+f"(c[1]), "+f"(c[2]), "+f"(c[3])
        : "r"(a[0]), "r"(a[1]), "r"(a[2]), "r"(a[3]), "r"(b[0]), "r"(b[1]));
}
__device__ __forceinline__ void cp_async16(uint32_t saddr, const void* gptr) {
    asm volatile("cp.async.cg.shared.global [%0], [%1], 16;" :: "r"(saddr), "l"(gptr));
}
#define CP_COMMIT() asm volatile("cp.async.commit_group;" ::: "memory")
#define CP_WAIT2()  asm volatile("cp.async.wait_group 2;" ::: "memory")
#define CP_WAIT1()  asm volatile("cp.async.wait_group 1;" ::: "memory")
#define CP_WAIT0()  asm volatile("cp.async.wait_group 0;" ::: "memory")
__device__ __forceinline__ uint32_t smem_u32(const void* p) {
    uint32_t a;
    asm("{ .reg .u64 t; cvta.to.shared.u64 t, %1; cvt.u32.u64 %0, t; }"
        : "=r"(a) : "l"(p));
    return a;
}

// ---------------- RMSNorm (bf16 output) -------------------------------------
__global__ __launch_bounds__(256) void rmsnorm_bf_kernel(
    const float* __restrict__ x, const float* __restrict__ w, __nv_bfloat16* __restrict__ out)
{
    int row = blockIdx.x;
    const float4* xr = (const float4*)(x + (size_t)row * DD);
    float4 xv = xr[threadIdx.x];
    float ss = xv.x*xv.x + xv.y*xv.y + xv.z*xv.z + xv.w*xv.w;
    #pragma unroll
    for (int o = 16; o > 0; o >>= 1) ss += __shfl_xor_sync(0xFFFFFFFFu, ss, o);
    __shared__ float red[8];
    if ((threadIdx.x & 31) == 0) red[threadIdx.x >> 5] = ss;
    __syncthreads();
    float tot = red[0]+red[1]+red[2]+red[3]+red[4]+red[5]+red[6]+red[7];
    float r = rsqrtf(tot * (1.0f/1024.0f) + 1e-5f);
    const float4* w4 = (const float4*)w;
    float4 wv = w4[threadIdx.x];
    __nv_bfloat162 lo = __floats2bfloat162_rn(xv.x*r*wv.x, xv.y*r*wv.y);
    __nv_bfloat162 hi = __floats2bfloat162_rn(xv.z*r*wv.z, xv.w*r*wv.w);
    uint2 pk;
    pk.x = *(uint32_t*)&lo;
    pk.y = *(uint32_t*)&hi;
    ((uint2*)(out + (size_t)row * DD))[threadIdx.x] = pk;
}

// ---------------- weight transpose fp32 [1024][Nn] -> bf16 [Nn][1024] -------
__global__ __launch_bounds__(256) void transpose_bf_kernel(
    const float* __restrict__ in, __nv_bfloat16* __restrict__ out, int Nn)
{
    __shared__ float t[32][33];
    int bx = blockIdx.x * 32;   // N dim
    int by = blockIdx.y * 32;   // K dim
    int x = threadIdx.x & 31;
    int y0 = threadIdx.x >> 5;
    #pragma unroll
    for (int y = y0; y < 32; y += 8)
        t[y][x] = in[(size_t)(by + y) * Nn + bx + x];
    __syncthreads();
    #pragma unroll
    for (int y = y0; y < 32; y += 8)
        out[(size_t)(bx + y) * 1024 + by + x] = __float2bfloat16(t[x][y]);
}

// ---------------- BF16 GEMM: BMx128x32, swizzled 64B rows, 3-stage ----------
// A bf16 [M][K] row-major, Bt bf16 [N][K].
// MODE 0: out bf16, no Cin. MODE 1: out fp32, + Cin. MODE 2: out fp32, no Cin.
__device__ __forceinline__ uint32_t bfswz(int r, int wcol) {
    return (uint32_t)(r * 64 + (((wcol >> 2) ^ ((r >> 1) & 3)) * 16) + (wcol & 3) * 4);
}

template<int BM, int MODE>
__global__ __launch_bounds__(BM * 2, 2) void bf_gemm(
    const __nv_bfloat16* __restrict__ A, const __nv_bfloat16* __restrict__ Bt,
    const float* __restrict__ Cin, float* __restrict__ Cf,
    __nv_bfloat16* __restrict__ Cbf, int Nn, int Kk)
{
    constexpr int THREADS = BM * 2;
    constexpr int AB_T = BM * 64;
    constexpr int STAGE_T = AB_T + 128 * 64;
    extern __shared__ char smem[];
    uint32_t sb = smem_u32(smem);
    int tid = threadIdx.x;
    const int brow = blockIdx.y * BM;
    const int bcol = blockIdx.x * 128;

    int w    = tid >> 5;
    int wm   = w >> 1;
    int wn   = w & 1;
    int lane = tid & 31;
    int grp  = lane >> 2;
    int qd   = lane & 3;

    float acc[2][8][4];
    #pragma unroll
    for (int i = 0; i < 2; i++)
        #pragma unroll
        for (int j = 0; j < 8; j++)
            #pragma unroll
            for (int q = 0; q < 4; q++) acc[i][j][q] = 0.f;

    const __nv_bfloat16* Ag = A  + (size_t)brow * Kk;
    const __nv_bfloat16* Bg = Bt + (size_t)bcol * Kk;
    const int ktiles = Kk / 32;

    #define LOAD_TILE_BF(kt, s) do {                                           \
        uint32_t ab = sb + (s) * STAGE_T;                                      \
        uint32_t bb = ab + AB_T;                                               \
        _Pragma("unroll")                                                      \
        for (int it = 0; it < (BM * 4) / THREADS; it++) {                      \
            int idx = it * THREADS + tid;                                      \
            int r = idx >> 2, kq = idx & 3;                                    \
            uint32_t so = (uint32_t)(r * 64 + ((kq ^ ((r >> 1) & 3)) * 16));   \
            cp_async16(ab + so, Ag + (size_t)r * Kk + (kt) * 32 + kq * 8);     \
        }                                                                      \
        _Pragma("unroll")                                                      \
        for (int it = 0; it < 512 / THREADS; it++) {                           \
            int idx = it * THREADS + tid;                                      \
            int r = idx >> 2, kq = idx & 3;                                    \
            uint32_t so = (uint32_t)(r * 64 + ((kq ^ ((r >> 1) & 3)) * 16));   \
            cp_async16(bb + so, Bg + (size_t)r * Kk + (kt) * 32 + kq * 8);     \
        }                                                                      \
        CP_COMMIT();                                                           \
    } while (0)

    LOAD_TILE_BF(0, 0);
    if (ktiles > 1) LOAD_TILE_BF(1, 1);

    for (int kt = 0; kt < ktiles; kt++) {
        int stg = kt - (kt / 3) * 3;
        if (kt + 2 < ktiles) {
            int s2 = (kt + 2) - ((kt + 2) / 3) * 3;
            LOAD_TILE_BF(kt + 2, s2);
            CP_WAIT2();
        } else if (kt + 1 < ktiles) {
            CP_WAIT1();
        } else {
            CP_WAIT0();
        }
        __syncthreads();

        const char* As = smem + stg * STAGE_T;
        const char* Bs = As + AB_T;

        #pragma unroll
        for (int s = 0; s < 2; s++) {           // two k16 steps
            uint32_t afr[2][4], bfr[8][2];
            int wc = s * 8 + qd;
            #pragma unroll
            for (int i = 0; i < 2; i++) {
                int r0 = wm * 32 + i * 16 + grp;
                afr[i][0] = *(const uint32_t*)(As + bfswz(r0,     wc));
                afr[i][1] = *(const uint32_t*)(As + bfswz(r0 + 8, wc));
                afr[i][2] = *(const uint32_t*)(As + bfswz(r0,     wc + 4));
                afr[i][3] = *(const uint32_t*)(As + bfswz(r0 + 8, wc + 4));
            }
            #pragma unroll
            for (int nt = 0; nt < 8; nt++) {
                int nn = wn * 64 + nt * 8 + grp;
                bfr[nt][0] = *(const uint32_t*)(Bs + bfswz(nn, wc));
                bfr[nt][1] = *(const uint32_t*)(Bs + bfswz(nn, wc + 4));
            }
            #pragma unroll
            for (int i = 0; i < 2; i++)
                #pragma unroll
                for (int nt = 0; nt < 8; nt++)
                    mma_bf16(acc[i][nt], afr[i], bfr[nt]);
        }
        __syncthreads();
    }

    #pragma unroll
    for (int i = 0; i < 2; i++) {
        size_t row0 = (size_t)brow + wm * 32 + i * 16 + grp;
        #pragma unroll
        for (int j = 0; j < 8; j++) {
            size_t col = (size_t)bcol + wn * 64 + j * 8 + qd * 2;
            if (MODE == 0) {
                __nv_bfloat162 p0 = __floats2bfloat162_rn(acc[i][j][0], acc[i][j][1]);
                __nv_bfloat162 p1 = __floats2bfloat162_rn(acc[i][j][2], acc[i][j][3]);
                *(__nv_bfloat162*)(Cbf + row0 * Nn + col) = p0;
                *(__nv_bfloat162*)(Cbf + (row0 + 8) * Nn + col) = p1;
            } else {
                float2 v0 = make_float2(acc[i][j][0], acc[i][j][1]);
                float2 v1 = make_float2(acc[i][j][2], acc[i][j][3]);
                if (MODE == 1) {
                    float2 r0 = *(const float2*)(Cin + row0 * Nn + col);
                    float2 r1 = *(const float2*)(Cin + (row0 + 8) * Nn + col);
                    v0.x += r0.x; v0.y += r0.y; v1.x += r1.x; v1.y += r1.y;
                }
                *(float2*)(Cf + row0 * Nn + col) = v0;
                *(float2*)(Cf + (row0 + 8) * Nn + col) = v1;
            }
        }
    }
    #undef LOAD_TILE_BF
}

#define GSMBF(BM) (3 * ((BM) * 64 + 128 * 64))

// ---------------- RoPE + repack ---------------------------------------------
__global__ __launch_bounds__(256) void rope_kernel()
{
    int idx = blockIdx.x * 256 + threadIdx.x;
    int d  = idx & 63;
    int hh = (idx >> 6) & 15;
    int t  = (idx >> 10) & 1023;
    int b  = idx >> 20;
    const float* base = g_qkv + (size_t)(b * 1024 + t) * 3072;
    float qv = base[hh * 64 + d];
    float kv = base[1024 + hh * 64 + d];
    float vv = base[2048 + hh * 64 + d];
    int i = d & 31;
    float inv = exp2f((float)i * (-13.287712379549449f / 32.0f));
    float f = (float)t * inv;
    float sn, cs;
    sincosf(f, &sn, &cs);
    float q2 = (d < 32) ? -base[hh*64 + d + 32] : base[hh*64 + d - 32];
    float k2 = (d < 32) ? -base[1024 + hh*64 + d + 32] : base[1024 + hh*64 + d - 32];
    size_t oi = ((size_t)(b * 16 + hh) * 1024 + t) * 64 + d;
    g_qr[oi] = qv * cs + q2 * sn;
    g_kr[oi] = kv * cs + k2 * sn;
    g_vb[oi] = vv;
}

// ---------------- Tensor-core flash attention (tf32, bf16 out) --------------
#define ATS 72
#define ATT_SMEM (3 * 64 * ATS * 4)

__global__ __launch_bounds__(128) void attn_tc_kernel()
{
    extern __shared__ float s[];
    float* QP = s;
    float* Ks = s + 64 * ATS;
    float* Vs = s + 2 * 64 * ATS;

    int bh = blockIdx.z * 16 + blockIdx.y;
    int q0 = blockIdx.x * 64;
    int tid = threadIdx.x;
    int w = tid >> 5, lane = tid & 31;
    int grp = lane >> 2, qd = lane & 3;
    int rr = w * 16 + grp;

    const float* Qg = g_qr + ((size_t)bh * 1024 + q0) * 64;
    #pragma unroll
    for (int it = 0; it < 8; it++) {
        int i = it * 128 + tid;
        int r = i >> 4, c = (i & 15) * 4;
        *(float4*)&QP[r * ATS + c] = *(const float4*)(Qg + (size_t)r * 64 + c);
    }
    __syncthreads();

    uint32_t qfr[8][4];
    #pragma unroll
    for (int k = 0; k < 8; k++) {
        qfr[k][0] = __float_as_uint(QP[rr * ATS + k * 8 + qd]);
        qfr[k][1] = __float_as_uint(QP[(rr + 8) * ATS + k * 8 + qd]);
        qfr[k][2] = __float_as_uint(QP[rr * ATS + k * 8 + qd + 4]);
        qfr[k][3] = __float_as_uint(QP[(rr + 8) * ATS + k * 8 + qd + 4]);
    }

    float m0 = -1e30f, m1 = -1e30f, l0 = 0.f, l1 = 0.f;
    float o[8][4];
    #pragma unroll
    for (int j = 0; j < 8; j++)
        #pragma unroll
        for (int q = 0; q < 4; q++) o[j][q] = 0.f;

    int row_g0 = q0 + rr;
    int row_g1 = row_g0 + 8;

    int ntiles = q0 / 64 + 1;
    for (int tIdx = 0; tIdx < ntiles; tIdx++) {
        int s0 = tIdx * 64;
        __syncthreads();
        const float* Kg = g_kr + ((size_t)bh * 1024 + s0) * 64;
        const float* Vg = g_vb + ((size_t)bh * 1024 + s0) * 64;
        #pragma unroll
        for (int it = 0; it < 8; it++) {
            int i = it * 128 + tid;
            int r = i >> 4, c = (i & 15) * 4;
            *(float4*)&Ks[r * ATS + c] = *(const float4*)(Kg + (size_t)r * 64 + c);
            *(float4*)&Vs[r * ATS + c] = *(const float4*)(Vg + (size_t)r * 64 + c);
        }
        __syncthreads();

        float sc[8][4];
        #pragma unroll
        for (int j = 0; j < 8; j++)
            #pragma unroll
            for (int q = 0; q < 4; q++) sc[j][q] = 0.f;
        #pragma unroll
        for (int k = 0; k < 8; k++) {
            int kb = k * 8;
            uint32_t bfr[8][2];
            #pragma unroll
            for (int nt = 0; nt < 8; nt++) {
                int nn = nt * 8 + grp;
                bfr[nt][0] = __float_as_uint(Ks[nn * ATS + kb + qd]);
                bfr[nt][1] = __float_as_uint(Ks[nn * ATS + kb + qd + 4]);
            }
            #pragma unroll
            for (int nt = 0; nt < 8; nt++)
                mma_tf32(sc[nt], qfr[k], bfr[nt]);
        }

        bool diag = (s0 == q0);
        #pragma unroll
        for (int nt = 0; nt < 8; nt++) {
            int c0 = s0 + nt * 8 + 2 * qd;
            sc[nt][0] *= 0.125f; sc[nt][1] *= 0.125f;
            sc[nt][2] *= 0.125f; sc[nt][3] *= 0.125f;
            if (diag) {
                if (c0 > row_g0)     sc[nt][0] = -1e30f;
                if (c0 + 1 > row_g0) sc[nt][1] = -1e30f;
                if (c0 > row_g1)     sc[nt][2] = -1e30f;
                if (c0 + 1 > row_g1) sc[nt][3] = -1e30f;
            }
        }

        float mt0 = -1e30f, mt1 = -1e30f;
        #pragma unroll
        for (int nt = 0; nt < 8; nt++) {
            mt0 = fmaxf(mt0, fmaxf(sc[nt][0], sc[nt][1]));
            mt1 = fmaxf(mt1, fmaxf(sc[nt][2], sc[nt][3]));
        }
        mt0 = fmaxf(mt0, __shfl_xor_sync(0xFFFFFFFFu, mt0, 1));
        mt0 = fmaxf(mt0, __shfl_xor_sync(0xFFFFFFFFu, mt0, 2));
        mt1 = fmaxf(mt1, __shfl_xor_sync(0xFFFFFFFFu, mt1, 1));
        mt1 = fmaxf(mt1, __shfl_xor_sync(0xFFFFFFFFu, mt1, 2));
        float mn0 = fmaxf(m0, mt0), mn1 = fmaxf(m1, mt1);
        float corr0 = __expf(m0 - mn0), corr1 = __expf(m1 - mn1);
        float sum0 = 0.f, sum1 = 0.f;
        #pragma unroll
        for (int nt = 0; nt < 8; nt++) {
            sc[nt][0] = __expf(sc[nt][0] - mn0);
            sc[nt][1] = __expf(sc[nt][1] - mn0);
            sc[nt][2] = __expf(sc[nt][2] - mn1);
            sc[nt][3] = __expf(sc[nt][3] - mn1);
            sum0 += sc[nt][0] + sc[nt][1];
            sum1 += sc[nt][2] + sc[nt][3];
        }
        sum0 += __shfl_xor_sync(0xFFFFFFFFu, sum0, 1);
        sum0 += __shfl_xor_sync(0xFFFFFFFFu, sum0, 2);
        sum1 += __shfl_xor_sync(0xFFFFFFFFu, sum1, 1);
        sum1 += __shfl_xor_sync(0xFFFFFFFFu, sum1, 2);
        l0 = l0 * corr0 + sum0;
        l1 = l1 * corr1 + sum1;
        m0 = mn0; m1 = mn1;

        #pragma unroll
        for (int nt = 0; nt < 8; nt++) {
            o[nt][0] *= corr0; o[nt][1] *= corr0;
            o[nt][2] *= corr1; o[nt][3] *= corr1;
            int cc = nt * 8 + 2 * qd;
            *(float2*)&QP[rr * ATS + cc]       = make_float2(sc[nt][0], sc[nt][1]);
            *(float2*)&QP[(rr + 8) * ATS + cc] = make_float2(sc[nt][2], sc[nt][3]);
        }
        __syncwarp();

        #pragma unroll
        for (int k = 0; k < 8; k++) {
            int kb = k * 8;
            uint32_t pa[4];
            pa[0] = __float_as_uint(QP[rr * ATS + kb + qd]);
            pa[1] = __float_as_uint(QP[(rr + 8) * ATS + kb + qd]);
            pa[2] = __float_as_uint(QP[rr * ATS + kb + qd + 4]);
            pa[3] = __float_as_uint(QP[(rr + 8) * ATS + kb + qd + 4]);
            uint32_t bfr[8][2];
            #pragma unroll
            for (int nt = 0; nt < 8; nt++) {
                int nn = nt * 8 + grp;
                bfr[nt][0] = __float_as_uint(Vs[(kb + qd) * ATS + nn]);
                bfr[nt][1] = __float_as_uint(Vs[(kb + qd + 4) * ATS + nn]);
            }
            #pragma unroll
            for (int nt = 0; nt < 8; nt++)
                mma_tf32(o[nt], pa, bfr[nt]);
        }
        __syncwarp();
    }

    float inv0 = 1.0f / l0, inv1 = 1.0f / l1;
    int b = bh >> 4, hh = bh & 15;
    size_t t0 = (size_t)(b * 1024) + q0 + rr;
    #pragma unroll
    for (int nt = 0; nt < 8; nt++) {
        int cc = nt * 8 + 2 * qd;
        *(__nv_bfloat162*)(g_obf + t0 * 1024 + hh * 64 + cc) =
            __floats2bfloat162_rn(o[nt][0] * inv0, o[nt][1] * inv0);
        *(__nv_bfloat162*)(g_obf + (t0 + 8) * 1024 + hh * 64 + cc) =
            __floats2bfloat162_rn(o[nt][2] * inv1, o[nt][3] * inv1);
    }
}

// ---------------- fused gate-softmax + sequential scan (bf16 out) -----------
#define RAW_F 2432
#define SCAN_SMEM ((2 * RAW_F + 2 * 4096 + 2 * 256 + 16) * 4)

__global__ __launch_bounds__(128) void scan_fused_kernel()
{
    extern __shared__ float ss[];
    float* raw[2] = { ss, ss + RAW_F };
    float* Ab [2] = { ss + 2 * RAW_F, ss + 2 * RAW_F + 4096 };
    float* bv [2] = { ss + 2 * RAW_F + 8192, ss + 2 * RAW_F + 8192 + 256 };
    float* st = ss + 2 * RAW_F + 8192 + 512;
    uint32_t raw_sb[2] = { smem_u32(raw[0]), smem_u32(raw[1]) };

    int bh = blockIdx.x;
    int b = bh >> 6, hh = bh & 63;
    int tid = threadIdx.x;
    int w = tid >> 5, lane = tid & 31;

    const char* gates_base = (const char*)(g_gates_bf) + ((size_t)b * 1024) * (NA * 2) + hh * 272 * 2;
    const char* vv_base    = (const char*)(g_vv)       + ((size_t)b * 1024) * (DD * 4) + hh * 16 * 4;

    #define LOAD_RAW(c, s, t0, nt) do {                                          \
        int base_t = (c) * 16;                                                   \
        for (int j = 0; j * (nt) < 608; j++) {                                   \
            int fid = j * (nt) + (tid - (t0));                                   \
            if (fid < 544) {                                                     \
                int tt = fid / 34, off = fid % 34;                               \
                cp_async16(raw_sb[s] + (uint32_t)(tt * 544 + off * 16),          \
                           gates_base + (size_t)(base_t + tt) * (NA * 2) + off * 16); \
            } else if (fid < 608) {                                              \
                int v = fid - 544;                                               \
                int tt = v >> 2, off = v & 3;                                    \
                cp_async16(raw_sb[s] + (uint32_t)(8704 + tt * 64 + off * 16),    \
                           vv_base + (size_t)(base_t + tt) * (DD * 4) + off * 16); \
            }                                                                    \
        }                                                                        \
        CP_COMMIT();                                                             \
    } while (0)

    #define SOFTMAX_ROW(r, s, a) do {                                            \
        int tt = (r) >> 4, ii = (r) & 15;                                        \
        const __nv_bfloat16* g = (const __nv_bfloat16*)raw[s] + tt * 272 + ii * 17; \
        float e[17]; float mx = -1e30f;                                          \
        _Pragma("unroll")                                                        \
        for (int k = 0; k < 17; k++) { e[k] = __bfloat162float(g[k]); mx = fmaxf(mx, e[k]); } \
        float sum = 0.f;                                                         \
        _Pragma("unroll")                                                        \
        for (int k = 0; k < 17; k++) { e[k] = __expf(e[k] - mx); sum += e[k]; }  \
        float inv = 1.0f / sum;                                                  \
        float* Ad = Ab[a] + tt * 256 + ii * 16;                                  \
        _Pragma("unroll")                                                        \
        for (int k = 0; k < 16; k++) Ad[k] = e[k + 1] * inv;                     \
        bv[a][tt * 16 + ii] = e[0] * inv * raw[s][2176 + tt * 16 + ii];          \
    } while (0)

    LOAD_RAW(0, 0, 0, 128);
    LOAD_RAW(1, 1, 0, 128);
    CP_WAIT0();
    __syncthreads();
    #pragma unroll
    for (int q = 0; q < 2; q++) {
        int r = q * 128 + tid;
        SOFTMAX_ROW(r, 0, 0);
    }
    if (tid < 16) st[tid] = 0.f;
    __syncthreads();

    for (int c = 0; c < 64; c++) {
        int cur = c & 1, nxt = cur ^ 1;
        if (w == 0) {
            if (lane < 16) {
                const float4* A4 = (const float4*)Ab[cur];
                const float* bvv = bv[cur];
                __nv_bfloat16* hrow = g_houtbf + ((size_t)(b * 1024 + c * 16)) * 1024 + hh * 16 + lane;
                #pragma unroll 4
                for (int s2 = 0; s2 < 16; s2++) {
                    float4 s0 = *(const float4*)&st[0];
                    float4 s1 = *(const float4*)&st[4];
                    float4 s2v = *(const float4*)&st[8];
                    float4 s3 = *(const float4*)&st[12];
                    float4 a0 = A4[s2 * 64 + lane * 4 + 0];
                    float4 a1 = A4[s2 * 64 + lane * 4 + 1];
                    float4 a2 = A4[s2 * 64 + lane * 4 + 2];
                    float4 a3 = A4[s2 * 64 + lane * 4 + 3];
                    float p0 = fmaf(a0.x, s0.x, fmaf(a0.y, s0.y, fmaf(a0.z, s0.z, a0.w * s0.w)));
                    float p1 = fmaf(a1.x, s1.x, fmaf(a1.y, s1.y, fmaf(a1.z, s1.z, a1.w * s1.w)));
                    float p2 = fmaf(a2.x, s2v.x, fmaf(a2.y, s2v.y, fmaf(a2.z, s2v.z, a2.w * s2v.w)));
                    float p3 = fmaf(a3.x, s3.x, fmaf(a3.y, s3.y, fmaf(a3.z, s3.z, a3.w * s3.w)));
                    float acc = bvv[s2 * 16 + lane] + ((p0 + p1) + (p2 + p3));
                    __syncwarp(0xFFFF);
                    st[lane] = acc;
                    __syncwarp(0xFFFF);
                    hrow[(size_t)s2 * 1024] = __float2bfloat16(acc);
                }
            }
        } else if (w >= 2) {
            if (c < 63) {
                #pragma unroll
                for (int q = 0; q < 4; q++) {
                    int r = (w - 2) * 32 + lane + q * 64;
                    SOFTMAX_ROW(r, nxt, nxt);
                }
            }
        } else {
            if (c + 2 < 64) {
                LOAD_RAW(c + 2, cur, 32, 32);
                CP_WAIT0();
            }
        }
        __syncthreads();
    }
    #undef LOAD_RAW
    #undef SOFTMAX_ROW
}

// ---------------- launch ----------------------------------------------------
extern "C" void kernel_launch(void* const* d_in, const int* in_sizes, int n_in,
                              void* d_out, int out_size)
{
    const float* x    = (const float*)d_in[0];
    const float* anw  = (const float*)d_in[1];
    const float* wqkv = (const float*)d_in[2];
    const float* wao  = (const float*)d_in[3];
    const float* lnw  = (const float*)d_in[4];
    const float* wv   = (const float*)d_in[5];
    const float* wa   = (const float*)d_in[6];
    const float* wop  = (const float*)d_in[7];
    float* out = (float*)d_out;

    float *pqkv, *px2, *pvv;
    __nv_bfloat16 *phbf, *pobf, *ph2bf, *phoutbf, *pgbf;
    __nv_bfloat16 *pwqkvt, *pwaot, *pwvt, *pwopt, *pwat;
    cudaGetSymbolAddress((void**)&phbf,   g_hbf);
    cudaGetSymbolAddress((void**)&pqkv,   g_qkv);
    cudaGetSymbolAddress((void**)&pobf,   g_obf);
    cudaGetSymbolAddress((void**)&px2,    g_x2);
    cudaGetSymbolAddress((void**)&ph2bf,  g_h2bf);
    cudaGetSymbolAddress((void**)&pvv,    g_vv);
    cudaGetSymbolAddress((void**)&phoutbf,g_houtbf);
    cudaGetSymbolAddress((void**)&pgbf,   g_gates_bf);
    cudaGetSymbolAddress((void**)&pwqkvt, g_wqkv_t);
    cudaGetSymbolAddress((void**)&pwaot,  g_wao_t);
    cudaGetSymbolAddress((void**)&pwvt,   g_wv_t);
    cudaGetSymbolAddress((void**)&pwopt,  g_wop_t);
    cudaGetSymbolAddress((void**)&pwat,   g_wat_bf);

    cudaFuncSetAttribute(bf_gemm<128,0>, cudaFuncAttributeMaxDynamicSharedMemorySize, GSMBF(128));
    cudaFuncSetAttribute(bf_gemm<128,2>, cudaFuncAttributeMaxDynamicSharedMemorySize, GSMBF(128));
    cudaFuncSetAttribute(bf_gemm<64,1>,  cudaFuncAttributeMaxDynamicSharedMemorySize, GSMBF(64));
    cudaFuncSetAttribute(bf_gemm<64,2>,  cudaFuncAttributeMaxDynamicSharedMemorySize, GSMBF(64));
    cudaFuncSetAttribute(attn_tc_kernel, cudaFuncAttributeMaxDynamicSharedMemorySize, ATT_SMEM);
    cudaFuncSetAttribute(scan_fused_kernel, cudaFuncAttributeMaxDynamicSharedMemorySize, SCAN_SMEM);

    // weight transposes (fp32 -> bf16, [K][N] -> [N][K])
    transpose_bf_kernel<<<dim3(3072/32, 32), 256>>>(wqkv, pwqkvt, 3072);
    transpose_bf_kernel<<<dim3(1024/32, 32), 256>>>(wao,  pwaot,  1024);
    transpose_bf_kernel<<<dim3(1024/32, 32), 256>>>(wv,   pwvt,   1024);
    transpose_bf_kernel<<<dim3(1024/32, 32), 256>>>(wop,  pwopt,  1024);
    transpose_bf_kernel<<<dim3(NA/32,   32), 256>>>(wa,   pwat,   NA);

    rmsnorm_bf_kernel<<<BT, 256>>>(x, anw, phbf);
    bf_gemm<128,2><<<dim3(3072/128, BT/128), 256, GSMBF(128)>>>(phbf, pwqkvt, nullptr, pqkv, nullptr, 3072, DD);
    rope_kernel<<<(2 * 1024 * 16 * 64) / 256, 256>>>();
    attn_tc_kernel<<<dim3(16, 16, 2), 128, ATT_SMEM>>>();
    bf_gemm<64,1><<<dim3(DD/128, BT/64), 128, GSMBF(64)>>>(pobf, pwaot, x, px2, nullptr, DD, DD);
    rmsnorm_bf_kernel<<<BT, 256>>>(px2, lnw, ph2bf);
    bf_gemm<64,2><<<dim3(DD/128, BT/64), 128, GSMBF(64)>>>(ph2bf, pwvt, nullptr, pvv, nullptr, DD, DD);
    bf_gemm<128,0><<<dim3(NA/128, BT/128), 256, GSMBF(128)>>>(ph2bf, pwat, nullptr, nullptr, pgbf, NA, DD);
    scan_fused_kernel<<<128, 128, SCAN_SMEM>>>();
    bf_gemm<64,1><<<dim3(DD/128, BT/64), 128, GSMBF(64)>>>(phoutbf, pwopt, px2, out, nullptr, DD, DD);
}